// round 3
// baseline (speedup 1.0000x reference)
#include <cuda_runtime.h>
#include <cstdint>

#define NROWS 131072
#define HALFN 65536
#define DDIM  512
#define HDIM  512
#define EPTN  65536

// Scratch for w2f = X @ W2[t] + b2[t]  (131072 x 512 f32 = 256 MiB)
__device__ float g_w2f[(size_t)NROWS * HDIM];

constexpr int BM = 128, BN = 128, BK = 16;

// One GEMM body, two epilogues:
//  EDGE=false: C[ry..][cx..] = A @ W[t] + b[t], t = row-half (proj kernels)
//  EDGE=true : per edge-row e: atomicAdd(out[src_e], acc + b5 + w2f[dst_e])
template<bool EDGE>
__global__ __launch_bounds__(256, 2)
void hetero_gemm_kernel(const float* __restrict__ A,
                        const float* __restrict__ W,
                        const float* __restrict__ bias,
                        float* __restrict__ C,
                        const int* __restrict__ edges,   // int32 pairs (src,dst)
                        float* __restrict__ out)
{
    __shared__ float As[BK][BM + 4];   // +4 pad: kills store bank conflicts
    __shared__ float Bs[BK][BN];

    const int ry = blockIdx.y * BM;
    const int cx = blockIdx.x * BN;

    int t = 0;
    if (!EDGE) t = (ry >= HALFN) ? 1 : 0;   // 65536 % 128 == 0 -> uniform per block
    const float* Wt = W + (size_t)t * DDIM * HDIM;
    const float* bt = bias + t * HDIM;

    const int tid  = threadIdx.x;
    const int tx   = tid & 15;
    const int ty   = tid >> 4;

    // global->smem load mapping
    const int arow = tid >> 2;          // 0..63
    const int acol = (tid & 3) << 2;    // 0,4,8,12
    const int brow = tid >> 5;          // 0..7
    const int bcol = (tid & 31) << 2;   // 0..124

    const float* Ag0 = A + (size_t)(ry + arow) * DDIM + acol;
    const float* Ag1 = Ag0 + (size_t)64 * DDIM;
    const float* Bg0 = Wt + (size_t)brow * HDIM + cx + bcol;
    const float* Bg1 = Bg0 + (size_t)8 * HDIM;

    float acc[8][8];
    #pragma unroll
    for (int i = 0; i < 8; i++)
        #pragma unroll
        for (int j = 0; j < 8; j++) acc[i][j] = 0.f;

    for (int k0 = 0; k0 < DDIM; k0 += BK) {
        const float4 a0 = *(const float4*)(Ag0 + k0);
        const float4 a1 = *(const float4*)(Ag1 + k0);
        const float4 b0 = *(const float4*)(Bg0 + (size_t)k0 * HDIM);
        const float4 b1 = *(const float4*)(Bg1 + (size_t)k0 * HDIM);
        __syncthreads();
        As[acol + 0][arow]      = a0.x; As[acol + 1][arow]      = a0.y;
        As[acol + 2][arow]      = a0.z; As[acol + 3][arow]      = a0.w;
        As[acol + 0][arow + 64] = a1.x; As[acol + 1][arow + 64] = a1.y;
        As[acol + 2][arow + 64] = a1.z; As[acol + 3][arow + 64] = a1.w;
        *(float4*)&Bs[brow    ][bcol] = b0;
        *(float4*)&Bs[brow + 8][bcol] = b1;
        __syncthreads();
        #pragma unroll
        for (int k = 0; k < BK; ++k) {
            const float4 af0 = *(const float4*)&As[k][ty * 8];
            const float4 af1 = *(const float4*)&As[k][ty * 8 + 4];
            const float4 bf0 = *(const float4*)&Bs[k][tx * 8];
            const float4 bf1 = *(const float4*)&Bs[k][tx * 8 + 4];
            const float a[8] = {af0.x, af0.y, af0.z, af0.w, af1.x, af1.y, af1.z, af1.w};
            const float b[8] = {bf0.x, bf0.y, bf0.z, bf0.w, bf1.x, bf1.y, bf1.z, bf1.w};
            #pragma unroll
            for (int i = 0; i < 8; i++)
                #pragma unroll
                for (int j = 0; j < 8; j++)
                    acc[i][j] = fmaf(a[i], b[j], acc[i][j]);
        }
    }

    const int col0 = cx + tx * 8;
    float bregs[8];
    #pragma unroll
    for (int j = 0; j < 8; j++) bregs[j] = bt[col0 + j];

    if (!EDGE) {
        #pragma unroll
        for (int i = 0; i < 8; i++) {
            const int r = ry + ty * 8 + i;
            const float4 v0 = make_float4(acc[i][0] + bregs[0], acc[i][1] + bregs[1],
                                          acc[i][2] + bregs[2], acc[i][3] + bregs[3]);
            const float4 v1 = make_float4(acc[i][4] + bregs[4], acc[i][5] + bregs[5],
                                          acc[i][6] + bregs[6], acc[i][7] + bregs[7]);
            *(float4*)(C + (size_t)r * HDIM + col0)     = v0;
            *(float4*)(C + (size_t)r * HDIM + col0 + 4) = v1;
        }
    } else {
        #pragma unroll
        for (int i = 0; i < 8; i++) {
            const int e = ry + ty * 8 + i;
            const int2 ed = *(const int2*)(edges + 2 * (size_t)e);  // int32 (src,dst)
            const int src = ed.x;
            const int dst = ed.y;
            // half-warp (same edge row) covers 512B contiguous -> coalesced
            const float4 w20 = *(const float4*)(g_w2f + (size_t)dst * HDIM + col0);
            const float4 w21 = *(const float4*)(g_w2f + (size_t)dst * HDIM + col0 + 4);
            float* op = out + (size_t)src * HDIM + col0;
            atomicAdd(op + 0, acc[i][0] + bregs[0] + w20.x);
            atomicAdd(op + 1, acc[i][1] + bregs[1] + w20.y);
            atomicAdd(op + 2, acc[i][2] + bregs[2] + w20.z);
            atomicAdd(op + 3, acc[i][3] + bregs[3] + w20.w);
            atomicAdd(op + 4, acc[i][4] + bregs[4] + w21.x);
            atomicAdd(op + 5, acc[i][5] + bregs[5] + w21.y);
            atomicAdd(op + 6, acc[i][6] + bregs[6] + w21.z);
            atomicAdd(op + 7, acc[i][7] + bregs[7] + w21.w);
        }
    }
}

extern "C" void kernel_launch(void* const* d_in, const int* in_sizes, int n_in,
                              void* d_out, int out_size)
{
    // metadata order: X E0 E1 W1 b1 W2 b2 W3 b3 W4 b4 W5 b5 edges0 edges1
    const float* X  = (const float*)d_in[0];
    const float* E0 = (const float*)d_in[1];
    const float* E1 = (const float*)d_in[2];
    const float* W1 = (const float*)d_in[3];
    const float* b1 = (const float*)d_in[4];
    const float* W2 = (const float*)d_in[5];
    const float* b2 = (const float*)d_in[6];
    // W3/b3/W4/b4 are dead: softmax over a singleton axis is identically 1.
    const float* W5 = (const float*)d_in[11];
    const float* b5 = (const float*)d_in[12];
    // JAX default config aliases int64 -> int32: edges are int32 pairs.
    const int* edges0 = (const int*)d_in[13];
    const int* edges1 = (const int*)d_in[14];
    float* out = (float*)d_out;

    float* w2f = nullptr;
    cudaGetSymbolAddress((void**)&w2f, g_w2f);   // no alloc; capture-safe

    dim3 blk(256);
    dim3 gproj(HDIM / BN, NROWS / BM);   // (4, 1024)
    dim3 gedge(HDIM / BN, EPTN / BM);    // (4, 512)

    // out = X @ W1[t] + b1[t]   (fully initializes d_out)
    hetero_gemm_kernel<false><<<gproj, blk>>>(X, W1, b1, out, nullptr, nullptr);
    // w2f = X @ W2[t] + b2[t]
    hetero_gemm_kernel<false><<<gproj, blk>>>(X, W2, b2, w2f, nullptr, nullptr);
    // t=0: out[src] += (E0 @ W5[0] + b5[0]) + w2f[dst]
    hetero_gemm_kernel<true><<<gedge, blk>>>(E0, W5, b5, nullptr, edges0, out);
    // t=1: out[src] += (E1 @ W5[1] + b5[1]) + w2f[dst]
    hetero_gemm_kernel<true><<<gedge, blk>>>(E1, W5 + (size_t)DDIM * HDIM, b5 + HDIM,
                                             nullptr, edges1, out);
}

// round 5
// speedup vs baseline: 1.7060x; 1.7060x over previous
#include <cuda_runtime.h>
#include <cuda_bf16.h>
#include <cstdint>

#define NROWS 131072
#define HALFN 65536
#define DDIM  512
#define HDIM  512
#define EPTN  65536

__device__ float g_w2f[(size_t)NROWS * HDIM];
__device__ __nv_bfloat16 g_wbh[6u * 512 * 512];   // [z=mat*2+t][n][k] hi
__device__ __nv_bfloat16 g_wbl[6u * 512 * 512];   // lo

// SMEM: per buffer A_HI 8K | A_LO 8K | B_HI 16K | B_LO 16K = 48K, x2 buffers
#define BUF_STRIDE 49152
#define OFF_A_HI 0
#define OFF_A_LO 8192
#define OFF_B_HI 16384
#define OFF_B_LO 32768
#define SMEM_TOTAL (2 * BUF_STRIDE)

#define SWZ64(o) ((o) ^ (((o) >> 3) & 0x30))

__device__ __forceinline__ uint32_t smem_u32(const void* p) {
    uint32_t a;
    asm("{ .reg .u64 t; cvta.to.shared.u64 t, %1; cvt.u32.u64 %0, t; }" : "=r"(a) : "l"(p));
    return a;
}
#define CPASYNC16(dst, src) asm volatile("cp.async.cg.shared.global [%0], [%1], 16;" :: "r"(dst), "l"(src))
#define CPCOMMIT() asm volatile("cp.async.commit_group;" ::: "memory")
#define CPWAIT0()  asm volatile("cp.async.wait_group 0;" ::: "memory")
#define LDSM4(r0, r1, r2, r3, ad) \
    asm volatile("ldmatrix.sync.aligned.m8n8.x4.shared.b16 {%0,%1,%2,%3}, [%4];" \
        : "=r"(r0), "=r"(r1), "=r"(r2), "=r"(r3) : "r"(ad))
#define MMA(d, a, b0, b1) \
    asm volatile("mma.sync.aligned.m16n8k16.row.col.f32.bf16.bf16.f32 " \
        "{%0,%1,%2,%3}, {%4,%5,%6,%7}, {%8,%9}, {%0,%1,%2,%3};" \
        : "+f"((d)[0]), "+f"((d)[1]), "+f"((d)[2]), "+f"((d)[3]) \
        : "r"((a)[0]), "r"((a)[1]), "r"((a)[2]), "r"((a)[3]), "r"(b0), "r"(b1))

__device__ __forceinline__ uint32_t pack_hi(float a, float b) {
    return (uint32_t)__bfloat16_as_ushort(__float2bfloat16(a)) |
           ((uint32_t)__bfloat16_as_ushort(__float2bfloat16(b)) << 16);
}
__device__ __forceinline__ uint32_t pack_lo(float a, float b) {
    float ra = a - __bfloat162float(__float2bfloat16(a));
    float rb = b - __bfloat162float(__float2bfloat16(b));
    return pack_hi(ra, rb);
}

// Transpose + bf16-split W1/W2/W5 into [z][n][k]
__global__ void prep_weights(const float* __restrict__ W1, const float* __restrict__ W2,
                             const float* __restrict__ W5) {
    __shared__ float tile[32][33];
    int z = blockIdx.z, mat = z >> 1, t = z & 1;
    const float* W = (mat == 0 ? W1 : mat == 1 ? W2 : W5) + (size_t)t * 512 * 512;
    int n0 = blockIdx.x * 32, k0 = blockIdx.y * 32;
    int lx = threadIdx.x & 31, ly = threadIdx.x >> 5;
    #pragma unroll
    for (int i = 0; i < 32; i += 8)
        tile[ly + i][lx] = W[(size_t)(k0 + ly + i) * 512 + n0 + lx];
    __syncthreads();
    size_t base = ((size_t)z * 512 + n0) * 512 + k0;
    #pragma unroll
    for (int i = 0; i < 32; i += 8) {
        float x = tile[lx][ly + i];
        __nv_bfloat16 h = __float2bfloat16(x);
        g_wbh[base + (size_t)(ly + i) * 512 + lx] = h;
        g_wbl[base + (size_t)(ly + i) * 512 + lx] = __float2bfloat16(x - __bfloat162float(h));
    }
}

template<bool EDGE>
__global__ __launch_bounds__(256, 1)
void mma_gemm(const float* __restrict__ A, int mat, int tparam,
              const float* __restrict__ bias, float* __restrict__ C,
              const int* __restrict__ edges, float* __restrict__ out)
{
    extern __shared__ char smem[];
    const uint32_t sb = smem_u32(smem);
    const int tid = threadIdx.x, wid = tid >> 5, lane = tid & 31;
    const int ry = blockIdx.y * 128;
    const int cx = blockIdx.x * 256;
    const int t = EDGE ? tparam : (ry >= HALFN ? 1 : 0);
    const int z = mat * 2 + t;
    const int wm = wid & 1, wn = wid >> 1;   // warp tile (wm*64, wn*64)

    // ---- fill mappings ----
    const int arow = tid >> 1, ahalf = tid & 1;
    const float4* Ag = (const float4*)(A + (size_t)(ry + arow) * DDIM);
    const __nv_bfloat16* BhG = g_wbh + ((size_t)z * 512 + cx + tid) * 512;
    const __nv_bfloat16* BlG = g_wbl + ((size_t)z * 512 + cx + tid) * 512;
    const uint32_t a_sts0 = SWZ64(arow * 64 + ahalf * 32);
    const uint32_t a_sts1 = SWZ64(arow * 64 + ahalf * 32 + 16);
    uint32_t b_dst[4];
    #pragma unroll
    for (int u = 0; u < 4; u++) b_dst[u] = SWZ64(tid * 64 + u * 16);

    // ---- ldmatrix per-lane offsets (chunk-independent) ----
    // A: row = wm*64 + mt*16 + (lane&15); kbyte = ks*32 + (lane>>4)*16
    uint32_t a_off[4][2];
    #pragma unroll
    for (int mt = 0; mt < 4; mt++)
        #pragma unroll
        for (int ks = 0; ks < 2; ks++)
            a_off[mt][ks] = SWZ64((wm * 64 + mt * 16 + (lane & 15)) * 64 +
                                  ks * 32 + (lane >> 4) * 16);
    // B: row = wn*64 + p*16 + (lane&7) + ((lane&16)?8:0); kbyte = ks*32 + ((lane&8)?16:0)
    uint32_t b_off[4][2];
    #pragma unroll
    for (int p = 0; p < 4; p++)
        #pragma unroll
        for (int ks = 0; ks < 2; ks++)
            b_off[p][ks] = SWZ64((wn * 64 + p * 16 + (lane & 7) + ((lane & 16) ? 8 : 0)) * 64 +
                                 ks * 32 + ((lane & 8) ? 16 : 0));

    float d[4][8][4];
    #pragma unroll
    for (int i = 0; i < 4; i++)
        #pragma unroll
        for (int j = 0; j < 8; j++)
            #pragma unroll
            for (int q = 0; q < 4; q++) d[i][j][q] = 0.f;

    // ---- prologue: fill buffer 0 (chunk 0) ----
    {
        float4 st[4];
        #pragma unroll
        for (int q = 0; q < 4; q++) st[q] = Ag[ahalf * 4 + q];
        #pragma unroll
        for (int u = 0; u < 4; u++) {
            CPASYNC16(sb + OFF_B_HI + b_dst[u], BhG + u * 8);
            CPASYNC16(sb + OFF_B_LO + b_dst[u], BlG + u * 8);
        }
        CPCOMMIT();
        uint4 hi0 = {pack_hi(st[0].x, st[0].y), pack_hi(st[0].z, st[0].w),
                     pack_hi(st[1].x, st[1].y), pack_hi(st[1].z, st[1].w)};
        uint4 hi1 = {pack_hi(st[2].x, st[2].y), pack_hi(st[2].z, st[2].w),
                     pack_hi(st[3].x, st[3].y), pack_hi(st[3].z, st[3].w)};
        uint4 lo0 = {pack_lo(st[0].x, st[0].y), pack_lo(st[0].z, st[0].w),
                     pack_lo(st[1].x, st[1].y), pack_lo(st[1].z, st[1].w)};
        uint4 lo1 = {pack_lo(st[2].x, st[2].y), pack_lo(st[2].z, st[2].w),
                     pack_lo(st[3].x, st[3].y), pack_lo(st[3].z, st[3].w)};
        *(uint4*)(smem + OFF_A_HI + a_sts0) = hi0;
        *(uint4*)(smem + OFF_A_HI + a_sts1) = hi1;
        *(uint4*)(smem + OFF_A_LO + a_sts0) = lo0;
        *(uint4*)(smem + OFF_A_LO + a_sts1) = lo1;
    }

    for (int c = 0; c < 16; c++) {
        const uint32_t buf  = sb + (c & 1) * BUF_STRIDE;
        const uint32_t nbuf = sb + ((c + 1) & 1) * BUF_STRIDE;
        CPWAIT0();
        __syncthreads();

        float4 st[4];
        if (c < 15) {
            #pragma unroll
            for (int q = 0; q < 4; q++) st[q] = Ag[(c + 1) * 8 + ahalf * 4 + q];
            #pragma unroll
            for (int u = 0; u < 4; u++) {
                CPASYNC16(nbuf + OFF_B_HI + b_dst[u], BhG + (c + 1) * 32 + u * 8);
                CPASYNC16(nbuf + OFF_B_LO + b_dst[u], BlG + (c + 1) * 32 + u * 8);
            }
            CPCOMMIT();
        }

        // ---- compute chunk c ----
        #pragma unroll
        for (int ks = 0; ks < 2; ks++) {
            uint32_t aH[4][4], aL[4][4], bH[8][2], bL[8][2];
            #pragma unroll
            for (int mt = 0; mt < 4; mt++) {
                LDSM4(aH[mt][0], aH[mt][1], aH[mt][2], aH[mt][3], buf + OFF_A_HI + a_off[mt][ks]);
                LDSM4(aL[mt][0], aL[mt][1], aL[mt][2], aL[mt][3], buf + OFF_A_LO + a_off[mt][ks]);
            }
            #pragma unroll
            for (int p = 0; p < 4; p++) {
                LDSM4(bH[2 * p][0], bH[2 * p][1], bH[2 * p + 1][0], bH[2 * p + 1][1],
                      buf + OFF_B_HI + b_off[p][ks]);
                LDSM4(bL[2 * p][0], bL[2 * p][1], bL[2 * p + 1][0], bL[2 * p + 1][1],
                      buf + OFF_B_LO + b_off[p][ks]);
            }
            #pragma unroll
            for (int mt = 0; mt < 4; mt++)
                #pragma unroll
                for (int n8 = 0; n8 < 8; n8++) {
                    MMA(d[mt][n8], aH[mt], bH[n8][0], bH[n8][1]);
                    MMA(d[mt][n8], aL[mt], bH[n8][0], bH[n8][1]);
                    MMA(d[mt][n8], aH[mt], bL[n8][0], bL[n8][1]);
                }
        }

        if (c < 15) {
            uint4 hi0 = {pack_hi(st[0].x, st[0].y), pack_hi(st[0].z, st[0].w),
                         pack_hi(st[1].x, st[1].y), pack_hi(st[1].z, st[1].w)};
            uint4 hi1 = {pack_hi(st[2].x, st[2].y), pack_hi(st[2].z, st[2].w),
                         pack_hi(st[3].x, st[3].y), pack_hi(st[3].z, st[3].w)};
            uint4 lo0 = {pack_lo(st[0].x, st[0].y), pack_lo(st[0].z, st[0].w),
                         pack_lo(st[1].x, st[1].y), pack_lo(st[1].z, st[1].w)};
            uint4 lo1 = {pack_lo(st[2].x, st[2].y), pack_lo(st[2].z, st[2].w),
                         pack_lo(st[3].x, st[3].y), pack_lo(st[3].z, st[3].w)};
            char* nb = smem + ((c + 1) & 1) * BUF_STRIDE;
            *(uint4*)(nb + OFF_A_HI + a_sts0) = hi0;
            *(uint4*)(nb + OFF_A_HI + a_sts1) = hi1;
            *(uint4*)(nb + OFF_A_LO + a_sts0) = lo0;
            *(uint4*)(nb + OFF_A_LO + a_sts1) = lo1;
        }
    }

    // ---- epilogue ----
    const float* bt = bias + (size_t)t * HDIM;
    const int c2 = (lane & 3) * 2, gr = lane >> 2;
    float2 bv[8];
    #pragma unroll
    for (int n8 = 0; n8 < 8; n8++)
        bv[n8] = *(const float2*)(bt + cx + wn * 64 + n8 * 8 + c2);

    if (!EDGE) {
        #pragma unroll
        for (int mt = 0; mt < 4; mt++) {
            const int r0 = ry + wm * 64 + mt * 16 + gr;
            float* p0 = C + (size_t)r0 * HDIM + cx + wn * 64 + c2;
            float* p1 = p0 + (size_t)8 * HDIM;
            #pragma unroll
            for (int n8 = 0; n8 < 8; n8++) {
                *(float2*)(p0 + n8 * 8) = make_float2(d[mt][n8][0] + bv[n8].x,
                                                      d[mt][n8][1] + bv[n8].y);
                *(float2*)(p1 + n8 * 8) = make_float2(d[mt][n8][2] + bv[n8].x,
                                                      d[mt][n8][3] + bv[n8].y);
            }
        }
    } else {
        #pragma unroll
        for (int mt = 0; mt < 4; mt++) {
            const int e0 = ry + wm * 64 + mt * 16 + gr;
            const int2 ea = ((const int2*)edges)[e0];
            const int2 eb = ((const int2*)edges)[e0 + 8];
            const float* wa = g_w2f + (size_t)ea.y * HDIM + cx + wn * 64 + c2;
            const float* wb = g_w2f + (size_t)eb.y * HDIM + cx + wn * 64 + c2;
            float* oa = out + (size_t)ea.x * HDIM + cx + wn * 64 + c2;
            float* ob = out + (size_t)eb.x * HDIM + cx + wn * 64 + c2;
            #pragma unroll
            for (int n8 = 0; n8 < 8; n8++) {
                float2 ga = *(const float2*)(wa + n8 * 8);
                float2 gb = *(const float2*)(wb + n8 * 8);
                atomicAdd(oa + n8 * 8 + 0, d[mt][n8][0] + bv[n8].x + ga.x);
                atomicAdd(oa + n8 * 8 + 1, d[mt][n8][1] + bv[n8].y + ga.y);
                atomicAdd(ob + n8 * 8 + 0, d[mt][n8][2] + bv[n8].x + gb.x);
                atomicAdd(ob + n8 * 8 + 1, d[mt][n8][3] + bv[n8].y + gb.y);
            }
        }
    }
}

extern "C" void kernel_launch(void* const* d_in, const int* in_sizes, int n_in,
                              void* d_out, int out_size)
{
    const float* X  = (const float*)d_in[0];
    const float* E0 = (const float*)d_in[1];
    const float* E1 = (const float*)d_in[2];
    const float* W1 = (const float*)d_in[3];
    const float* b1 = (const float*)d_in[4];
    const float* W2 = (const float*)d_in[5];
    const float* b2 = (const float*)d_in[6];
    const float* W5 = (const float*)d_in[11];
    const float* b5 = (const float*)d_in[12];
    const int* edges0 = (const int*)d_in[13];   // JAX x64-disabled: int32 pairs
    const int* edges1 = (const int*)d_in[14];
    float* out = (float*)d_out;

    float* w2f = nullptr;
    cudaGetSymbolAddress((void**)&w2f, g_w2f);

    cudaFuncSetAttribute(mma_gemm<false>, cudaFuncAttributeMaxDynamicSharedMemorySize, SMEM_TOTAL);
    cudaFuncSetAttribute(mma_gemm<true>,  cudaFuncAttributeMaxDynamicSharedMemorySize, SMEM_TOTAL);

    prep_weights<<<dim3(16, 16, 6), 256>>>(W1, W2, W5);
    // out = X@W1[t] + b1[t]   (softmax over singleton axis == 1 -> W3/W4 dead)
    mma_gemm<false><<<dim3(2, 1024), 256, SMEM_TOTAL>>>(X, 0, 0, b1, out, nullptr, nullptr);
    // w2f = X@W2[t] + b2[t]
    mma_gemm<false><<<dim3(2, 1024), 256, SMEM_TOTAL>>>(X, 1, 0, b2, w2f, nullptr, nullptr);
    // out[src] += (E@W5[t] + b5[t]) + w2f[dst]
    mma_gemm<true><<<dim3(2, 512), 256, SMEM_TOTAL>>>(E0, 2, 0, b5, nullptr, edges0, out);
    mma_gemm<true><<<dim3(2, 512), 256, SMEM_TOTAL>>>(E1, 2, 1, b5, nullptr, edges1, out);
}

// round 6
// speedup vs baseline: 2.2350x; 1.3101x over previous
#include <cuda_runtime.h>
#include <cuda_bf16.h>
#include <cstdint>

#define NROWS 131072
#define HALFN 65536
#define DDIM  512
#define HDIM  512
#define EPTN  65536

__device__ float g_w2f[(size_t)NROWS * HDIM];
__device__ __nv_bfloat16 g_wbh[6u * 512 * 512];   // [z=mat*2+t][n][k] hi
__device__ __nv_bfloat16 g_wbl[6u * 512 * 512];   // lo

// SMEM per buffer: A_HI 8K | A_LO 8K | B_HI 8K | B_LO 8K = 32K, x2 buffers
#define BUF_STRIDE 32768
#define OFF_A_HI 0
#define OFF_A_LO 8192
#define OFF_B_HI 16384
#define OFF_B_LO 24576
#define SMEM_TOTAL (2 * BUF_STRIDE)

#define SWZ64(o) ((o) ^ (((o) >> 3) & 0x30))

__device__ __forceinline__ uint32_t smem_u32(const void* p) {
    uint32_t a;
    asm("{ .reg .u64 t; cvta.to.shared.u64 t, %1; cvt.u32.u64 %0, t; }" : "=r"(a) : "l"(p));
    return a;
}
#define CPASYNC16(dst, src) asm volatile("cp.async.cg.shared.global [%0], [%1], 16;" :: "r"(dst), "l"(src))
#define CPCOMMIT() asm volatile("cp.async.commit_group;" ::: "memory")
#define CPWAIT0()  asm volatile("cp.async.wait_group 0;" ::: "memory")
#define LDSM4(r0, r1, r2, r3, ad) \
    asm volatile("ldmatrix.sync.aligned.m8n8.x4.shared.b16 {%0,%1,%2,%3}, [%4];" \
        : "=r"(r0), "=r"(r1), "=r"(r2), "=r"(r3) : "r"(ad))
#define MMA(d, a, b0, b1) \
    asm volatile("mma.sync.aligned.m16n8k16.row.col.f32.bf16.bf16.f32 " \
        "{%0,%1,%2,%3}, {%4,%5,%6,%7}, {%8,%9}, {%0,%1,%2,%3};" \
        : "+f"((d)[0]), "+f"((d)[1]), "+f"((d)[2]), "+f"((d)[3]) \
        : "r"((a)[0]), "r"((a)[1]), "r"((a)[2]), "r"((a)[3]), "r"(b0), "r"(b1))

__device__ __forceinline__ uint32_t pack_hi(float a, float b) {
    return (uint32_t)__bfloat16_as_ushort(__float2bfloat16(a)) |
           ((uint32_t)__bfloat16_as_ushort(__float2bfloat16(b)) << 16);
}
__device__ __forceinline__ uint32_t pack_lo(float a, float b) {
    float ra = a - __bfloat162float(__float2bfloat16(a));
    float rb = b - __bfloat162float(__float2bfloat16(b));
    return pack_hi(ra, rb);
}

// Transpose + bf16-split W1/W2/W5 into [z][n][k]
__global__ void prep_weights(const float* __restrict__ W1, const float* __restrict__ W2,
                             const float* __restrict__ W5) {
    __shared__ float tile[32][33];
    int z = blockIdx.z, mat = z >> 1, t = z & 1;
    const float* W = (mat == 0 ? W1 : mat == 1 ? W2 : W5) + (size_t)t * 512 * 512;
    int n0 = blockIdx.x * 32, k0 = blockIdx.y * 32;
    int lx = threadIdx.x & 31, ly = threadIdx.x >> 5;
    #pragma unroll
    for (int i = 0; i < 32; i += 8)
        tile[ly + i][lx] = W[(size_t)(k0 + ly + i) * 512 + n0 + lx];
    __syncthreads();
    size_t base = ((size_t)z * 512 + n0) * 512 + k0;
    #pragma unroll
    for (int i = 0; i < 32; i += 8) {
        float x = tile[lx][ly + i];
        __nv_bfloat16 h = __float2bfloat16(x);
        g_wbh[base + (size_t)(ly + i) * 512 + lx] = h;
        g_wbl[base + (size_t)(ly + i) * 512 + lx] = __float2bfloat16(x - __bfloat162float(h));
    }
}

template<bool EDGE>
__global__ __launch_bounds__(256, 2)
void mma_gemm(const float* __restrict__ A, int mat, int tparam,
              const float* __restrict__ bias, float* __restrict__ C,
              const int* __restrict__ edges, float* __restrict__ out)
{
    extern __shared__ char smem[];
    const uint32_t sb = smem_u32(smem);
    const int tid = threadIdx.x, wid = tid >> 5, lane = tid & 31;
    const int ry = blockIdx.y * 128;
    const int cx = blockIdx.x * 128;
    const int t = EDGE ? tparam : (ry >= HALFN ? 1 : 0);
    const int z = mat * 2 + t;
    const int wm = wid & 3, wn = wid >> 2;   // warp tile (wm*32, wn*64)

    // ---- fill mappings ----
    const int arow = tid >> 1, ahalf = tid & 1;      // A: 2 thr/row, 16 floats each
    const float4* Ag = (const float4*)(A + (size_t)(ry + arow) * DDIM);
    const int brow = tid >> 1, bhalf = tid & 1;      // B: 2 thr/row, 16 bf16 each
    const __nv_bfloat16* BhG = g_wbh + ((size_t)z * 512 + cx + brow) * 512 + bhalf * 16;
    const __nv_bfloat16* BlG = g_wbl + ((size_t)z * 512 + cx + brow) * 512 + bhalf * 16;
    const uint32_t a_sts0 = SWZ64(arow * 64 + ahalf * 32);
    const uint32_t a_sts1 = SWZ64(arow * 64 + ahalf * 32 + 16);
    const uint32_t b_dst0 = SWZ64(brow * 64 + bhalf * 32);
    const uint32_t b_dst1 = SWZ64(brow * 64 + bhalf * 32 + 16);

    // ---- ldmatrix per-lane offsets (chunk-independent) ----
    uint32_t a_off[2][2];
    #pragma unroll
    for (int mt = 0; mt < 2; mt++)
        #pragma unroll
        for (int ks = 0; ks < 2; ks++)
            a_off[mt][ks] = SWZ64((wm * 32 + mt * 16 + (lane & 15)) * 64 +
                                  ks * 32 + (lane >> 4) * 16);
    uint32_t b_off[4][2];
    #pragma unroll
    for (int p = 0; p < 4; p++)
        #pragma unroll
        for (int ks = 0; ks < 2; ks++)
            b_off[p][ks] = SWZ64((wn * 64 + p * 16 + (lane & 7) + ((lane & 16) ? 8 : 0)) * 64 +
                                 ks * 32 + ((lane & 8) ? 16 : 0));

    float d[2][8][4];
    #pragma unroll
    for (int i = 0; i < 2; i++)
        #pragma unroll
        for (int j = 0; j < 8; j++)
            #pragma unroll
            for (int q = 0; q < 4; q++) d[i][j][q] = 0.f;

    // ---- prologue: fill buffer 0 (chunk 0) ----
    {
        float4 st[4];
        #pragma unroll
        for (int q = 0; q < 4; q++) st[q] = Ag[ahalf * 4 + q];
        CPASYNC16(sb + OFF_B_HI + b_dst0, BhG);
        CPASYNC16(sb + OFF_B_HI + b_dst1, BhG + 8);
        CPASYNC16(sb + OFF_B_LO + b_dst0, BlG);
        CPASYNC16(sb + OFF_B_LO + b_dst1, BlG + 8);
        CPCOMMIT();
        uint4 hi0 = {pack_hi(st[0].x, st[0].y), pack_hi(st[0].z, st[0].w),
                     pack_hi(st[1].x, st[1].y), pack_hi(st[1].z, st[1].w)};
        uint4 hi1 = {pack_hi(st[2].x, st[2].y), pack_hi(st[2].z, st[2].w),
                     pack_hi(st[3].x, st[3].y), pack_hi(st[3].z, st[3].w)};
        uint4 lo0 = {pack_lo(st[0].x, st[0].y), pack_lo(st[0].z, st[0].w),
                     pack_lo(st[1].x, st[1].y), pack_lo(st[1].z, st[1].w)};
        uint4 lo1 = {pack_lo(st[2].x, st[2].y), pack_lo(st[2].z, st[2].w),
                     pack_lo(st[3].x, st[3].y), pack_lo(st[3].z, st[3].w)};
        *(uint4*)(smem + OFF_A_HI + a_sts0) = hi0;
        *(uint4*)(smem + OFF_A_HI + a_sts1) = hi1;
        *(uint4*)(smem + OFF_A_LO + a_sts0) = lo0;
        *(uint4*)(smem + OFF_A_LO + a_sts1) = lo1;
    }

    for (int c = 0; c < 16; c++) {
        const uint32_t buf  = sb + (c & 1) * BUF_STRIDE;
        const uint32_t nbuf = sb + ((c + 1) & 1) * BUF_STRIDE;
        CPWAIT0();
        __syncthreads();

        float4 st[4];
        if (c < 15) {
            #pragma unroll
            for (int q = 0; q < 4; q++) st[q] = Ag[(c + 1) * 8 + ahalf * 4 + q];
            CPASYNC16(nbuf + OFF_B_HI + b_dst0, BhG + (c + 1) * 32);
            CPASYNC16(nbuf + OFF_B_HI + b_dst1, BhG + (c + 1) * 32 + 8);
            CPASYNC16(nbuf + OFF_B_LO + b_dst0, BlG + (c + 1) * 32);
            CPASYNC16(nbuf + OFF_B_LO + b_dst1, BlG + (c + 1) * 32 + 8);
            CPCOMMIT();
        }

        // ---- compute chunk c ----
        #pragma unroll
        for (int ks = 0; ks < 2; ks++) {
            uint32_t aH[2][4], aL[2][4];
            #pragma unroll
            for (int mt = 0; mt < 2; mt++) {
                LDSM4(aH[mt][0], aH[mt][1], aH[mt][2], aH[mt][3], buf + OFF_A_HI + a_off[mt][ks]);
                LDSM4(aL[mt][0], aL[mt][1], aL[mt][2], aL[mt][3], buf + OFF_A_LO + a_off[mt][ks]);
            }
            #pragma unroll
            for (int p = 0; p < 4; p++) {
                uint32_t bh[4], bl[4];
                LDSM4(bh[0], bh[1], bh[2], bh[3], buf + OFF_B_HI + b_off[p][ks]);
                LDSM4(bl[0], bl[1], bl[2], bl[3], buf + OFF_B_LO + b_off[p][ks]);
                #pragma unroll
                for (int mt = 0; mt < 2; mt++) {
                    MMA(d[mt][2 * p],     aH[mt], bh[0], bh[1]);
                    MMA(d[mt][2 * p],     aL[mt], bh[0], bh[1]);
                    MMA(d[mt][2 * p],     aH[mt], bl[0], bl[1]);
                    MMA(d[mt][2 * p + 1], aH[mt], bh[2], bh[3]);
                    MMA(d[mt][2 * p + 1], aL[mt], bh[2], bh[3]);
                    MMA(d[mt][2 * p + 1], aH[mt], bl[2], bl[3]);
                }
            }
        }

        if (c < 15) {
            uint4 hi0 = {pack_hi(st[0].x, st[0].y), pack_hi(st[0].z, st[0].w),
                         pack_hi(st[1].x, st[1].y), pack_hi(st[1].z, st[1].w)};
            uint4 hi1 = {pack_hi(st[2].x, st[2].y), pack_hi(st[2].z, st[2].w),
                         pack_hi(st[3].x, st[3].y), pack_hi(st[3].z, st[3].w)};
            uint4 lo0 = {pack_lo(st[0].x, st[0].y), pack_lo(st[0].z, st[0].w),
                         pack_lo(st[1].x, st[1].y), pack_lo(st[1].z, st[1].w)};
            uint4 lo1 = {pack_lo(st[2].x, st[2].y), pack_lo(st[2].z, st[2].w),
                         pack_lo(st[3].x, st[3].y), pack_lo(st[3].z, st[3].w)};
            char* nb = smem + ((c + 1) & 1) * BUF_STRIDE;
            *(uint4*)(nb + OFF_A_HI + a_sts0) = hi0;
            *(uint4*)(nb + OFF_A_HI + a_sts1) = hi1;
            *(uint4*)(nb + OFF_A_LO + a_sts0) = lo0;
            *(uint4*)(nb + OFF_A_LO + a_sts1) = lo1;
        }
    }

    // ---- epilogue ----
    const float* bt = bias + (size_t)t * HDIM;
    const int c2 = (lane & 3) * 2, gr = lane >> 2;
    float2 bv[8];
    #pragma unroll
    for (int n8 = 0; n8 < 8; n8++)
        bv[n8] = *(const float2*)(bt + cx + wn * 64 + n8 * 8 + c2);

    if (!EDGE) {
        #pragma unroll
        for (int mt = 0; mt < 2; mt++) {
            const int r0 = ry + wm * 32 + mt * 16 + gr;
            float* p0 = C + (size_t)r0 * HDIM + cx + wn * 64 + c2;
            float* p1 = p0 + (size_t)8 * HDIM;
            #pragma unroll
            for (int n8 = 0; n8 < 8; n8++) {
                *(float2*)(p0 + n8 * 8) = make_float2(d[mt][n8][0] + bv[n8].x,
                                                      d[mt][n8][1] + bv[n8].y);
                *(float2*)(p1 + n8 * 8) = make_float2(d[mt][n8][2] + bv[n8].x,
                                                      d[mt][n8][3] + bv[n8].y);
            }
        }
    } else {
        #pragma unroll
        for (int mt = 0; mt < 2; mt++) {
            const int e0 = ry + wm * 32 + mt * 16 + gr;
            const int2 ea = ((const int2*)edges)[e0];
            const int2 eb = ((const int2*)edges)[e0 + 8];
            const float* wa = g_w2f + (size_t)ea.y * HDIM + cx + wn * 64 + c2;
            const float* wb = g_w2f + (size_t)eb.y * HDIM + cx + wn * 64 + c2;
            float* oa = out + (size_t)ea.x * HDIM + cx + wn * 64 + c2;
            float* ob = out + (size_t)eb.x * HDIM + cx + wn * 64 + c2;
            #pragma unroll
            for (int n8 = 0; n8 < 8; n8++) {
                float2 ga = *(const float2*)(wa + n8 * 8);
                float2 gb = *(const float2*)(wb + n8 * 8);
                atomicAdd(oa + n8 * 8 + 0, d[mt][n8][0] + bv[n8].x + ga.x);
                atomicAdd(oa + n8 * 8 + 1, d[mt][n8][1] + bv[n8].y + ga.y);
                atomicAdd(ob + n8 * 8 + 0, d[mt][n8][2] + bv[n8].x + gb.x);
                atomicAdd(ob + n8 * 8 + 1, d[mt][n8][3] + bv[n8].y + gb.y);
            }
        }
    }
}

extern "C" void kernel_launch(void* const* d_in, const int* in_sizes, int n_in,
                              void* d_out, int out_size)
{
    const float* X  = (const float*)d_in[0];
    const float* E0 = (const float*)d_in[1];
    const float* E1 = (const float*)d_in[2];
    const float* W1 = (const float*)d_in[3];
    const float* b1 = (const float*)d_in[4];
    const float* W2 = (const float*)d_in[5];
    const float* b2 = (const float*)d_in[6];
    const float* W5 = (const float*)d_in[11];
    const float* b5 = (const float*)d_in[12];
    const int* edges0 = (const int*)d_in[13];   // JAX x64-disabled: int32 pairs
    const int* edges1 = (const int*)d_in[14];
    float* out = (float*)d_out;

    float* w2f = nullptr;
    cudaGetSymbolAddress((void**)&w2f, g_w2f);

    cudaFuncSetAttribute(mma_gemm<false>, cudaFuncAttributeMaxDynamicSharedMemorySize, SMEM_TOTAL);
    cudaFuncSetAttribute(mma_gemm<true>,  cudaFuncAttributeMaxDynamicSharedMemorySize, SMEM_TOTAL);

    prep_weights<<<dim3(16, 16, 6), 256>>>(W1, W2, W5);
    // out = X@W1[t] + b1[t]   (softmax over singleton axis == 1 -> W3/W4 dead)
    mma_gemm<false><<<dim3(4, 1024), 256, SMEM_TOTAL>>>(X, 0, 0, b1, out, nullptr, nullptr);
    // w2f = X@W2[t] + b2[t]
    mma_gemm<false><<<dim3(4, 1024), 256, SMEM_TOTAL>>>(X, 1, 0, b2, w2f, nullptr, nullptr);
    // out[src] += (E@W5[t] + b5[t]) + w2f[dst]
    mma_gemm<true><<<dim3(4, 512), 256, SMEM_TOTAL>>>(E0, 2, 0, b5, nullptr, edges0, out);
    mma_gemm<true><<<dim3(4, 512), 256, SMEM_TOTAL>>>(E1, 2, 1, b5, nullptr, edges1, out);
}

// round 7
// speedup vs baseline: 2.3033x; 1.0306x over previous
#include <cuda_runtime.h>
#include <cuda_bf16.h>
#include <cstdint>

#define NROWS 131072
#define HALFN 65536
#define DDIM  512
#define HDIM  512
#define EPTN  65536

__device__ float g_w2f[(size_t)NROWS * HDIM];
__device__ __nv_bfloat16 g_wbh[6u * 512 * 512];   // [z=mat*2+t][n][k] hi
__device__ __nv_bfloat16 g_wbl[6u * 512 * 512];   // lo

// SMEM per buffer: A_HI 8K | A_LO 8K | B_HI 8K | B_LO 8K = 32K, x2 buffers
#define BUF_STRIDE 32768
#define OFF_A_HI 0
#define OFF_A_LO 8192
#define OFF_B_HI 16384
#define OFF_B_LO 24576
#define SMEM_TOTAL (2 * BUF_STRIDE)

#define SWZ64(o) ((o) ^ (((o) >> 3) & 0x30))

__device__ __forceinline__ uint32_t smem_u32(const void* p) {
    uint32_t a;
    asm("{ .reg .u64 t; cvta.to.shared.u64 t, %1; cvt.u32.u64 %0, t; }" : "=r"(a) : "l"(p));
    return a;
}
#define CPASYNC16(dst, src) asm volatile("cp.async.cg.shared.global [%0], [%1], 16;" :: "r"(dst), "l"(src))
#define CPCOMMIT() asm volatile("cp.async.commit_group;" ::: "memory")
#define CPWAIT0()  asm volatile("cp.async.wait_group 0;" ::: "memory")
#define LDSM4(r0, r1, r2, r3, ad) \
    asm volatile("ldmatrix.sync.aligned.m8n8.x4.shared.b16 {%0,%1,%2,%3}, [%4];" \
        : "=r"(r0), "=r"(r1), "=r"(r2), "=r"(r3) : "r"(ad))
#define MMA(d, a, b0, b1) \
    asm volatile("mma.sync.aligned.m16n8k16.row.col.f32.bf16.bf16.f32 " \
        "{%0,%1,%2,%3}, {%4,%5,%6,%7}, {%8,%9}, {%0,%1,%2,%3};" \
        : "+f"((d)[0]), "+f"((d)[1]), "+f"((d)[2]), "+f"((d)[3]) \
        : "r"((a)[0]), "r"((a)[1]), "r"((a)[2]), "r"((a)[3]), "r"(b0), "r"(b1))

__device__ __forceinline__ uint32_t pack_hi(float a, float b) {
    return (uint32_t)__bfloat16_as_ushort(__float2bfloat16(a)) |
           ((uint32_t)__bfloat16_as_ushort(__float2bfloat16(b)) << 16);
}
__device__ __forceinline__ uint32_t pack_lo(float a, float b) {
    float ra = a - __bfloat162float(__float2bfloat16(a));
    float rb = b - __bfloat162float(__float2bfloat16(b));
    return pack_hi(ra, rb);
}

// Transpose + bf16-split W1/W2/W5 into [z][n][k]
__global__ void prep_weights(const float* __restrict__ W1, const float* __restrict__ W2,
                             const float* __restrict__ W5) {
    __shared__ float tile[32][33];
    int z = blockIdx.z, mat = z >> 1, t = z & 1;
    const float* W = (mat == 0 ? W1 : mat == 1 ? W2 : W5) + (size_t)t * 512 * 512;
    int n0 = blockIdx.x * 32, k0 = blockIdx.y * 32;
    int lx = threadIdx.x & 31, ly = threadIdx.x >> 5;
    #pragma unroll
    for (int i = 0; i < 32; i += 8)
        tile[ly + i][lx] = W[(size_t)(k0 + ly + i) * 512 + n0 + lx];
    __syncthreads();
    size_t base = ((size_t)z * 512 + n0) * 512 + k0;
    #pragma unroll
    for (int i = 0; i < 32; i += 8) {
        float x = tile[lx][ly + i];
        __nv_bfloat16 h = __float2bfloat16(x);
        g_wbh[base + (size_t)(ly + i) * 512 + lx] = h;
        g_wbl[base + (size_t)(ly + i) * 512 + lx] = __float2bfloat16(x - __bfloat162float(h));
    }
}

// EDGE=false: fused dual-proj. blockIdx.x in [0,8): mat = bx>>2 (0->W1/out, 1->W2/w2f).
// EDGE=true : edge GEMM + gather/scatter epilogue (mat=2).
template<bool EDGE>
__global__ __launch_bounds__(256, 2)
void mma_gemm(const float* __restrict__ A, int tparam,
              const float* __restrict__ bias1, const float* __restrict__ bias2,
              float* __restrict__ C1, float* __restrict__ C2,
              const int* __restrict__ edges, float* __restrict__ out)
{
    extern __shared__ char smem[];
    const uint32_t sb = smem_u32(smem);
    const int tid = threadIdx.x, wid = tid >> 5, lane = tid & 31;
    const int bx = blockIdx.x;
    const int ry = blockIdx.y * 128;
    const int cx = (EDGE ? bx : (bx & 3)) * 128;
    const int mat = EDGE ? 2 : (bx >> 2);
    const int t = EDGE ? tparam : (ry >= HALFN ? 1 : 0);
    const int z = mat * 2 + t;
    const int wm = wid & 3, wn = wid >> 2;   // warp tile (wm*32, wn*64)

    // ---- fill mappings ----
    const int arow = tid >> 1, ahalf = tid & 1;      // A: 2 thr/row, 16 floats each
    const float4* Ag = (const float4*)(A + (size_t)(ry + arow) * DDIM);
    const int brow = tid >> 1, bhalf = tid & 1;      // B: 2 thr/row, 16 bf16 each
    const __nv_bfloat16* BhG = g_wbh + ((size_t)z * 512 + cx + brow) * 512 + bhalf * 16;
    const __nv_bfloat16* BlG = g_wbl + ((size_t)z * 512 + cx + brow) * 512 + bhalf * 16;
    const uint32_t a_sts0 = SWZ64(arow * 64 + ahalf * 32);
    const uint32_t a_sts1 = SWZ64(arow * 64 + ahalf * 32 + 16);
    const uint32_t b_dst0 = SWZ64(brow * 64 + bhalf * 32);
    const uint32_t b_dst1 = SWZ64(brow * 64 + bhalf * 32 + 16);

    // ---- ldmatrix per-lane offsets (chunk-independent) ----
    uint32_t a_off[2][2];
    #pragma unroll
    for (int mt = 0; mt < 2; mt++)
        #pragma unroll
        for (int ks = 0; ks < 2; ks++)
            a_off[mt][ks] = SWZ64((wm * 32 + mt * 16 + (lane & 15)) * 64 +
                                  ks * 32 + (lane >> 4) * 16);
    uint32_t b_off[4][2];
    #pragma unroll
    for (int p = 0; p < 4; p++)
        #pragma unroll
        for (int ks = 0; ks < 2; ks++)
            b_off[p][ks] = SWZ64((wn * 64 + p * 16 + (lane & 7) + ((lane & 16) ? 8 : 0)) * 64 +
                                 ks * 32 + ((lane & 8) ? 16 : 0));

    float d[2][8][4];
    #pragma unroll
    for (int i = 0; i < 2; i++)
        #pragma unroll
        for (int j = 0; j < 8; j++)
            #pragma unroll
            for (int q = 0; q < 4; q++) d[i][j][q] = 0.f;

    // ---- prologue: fill buffer 0 (chunk 0) ----
    {
        float4 st[4];
        #pragma unroll
        for (int q = 0; q < 4; q++) st[q] = Ag[ahalf * 4 + q];
        CPASYNC16(sb + OFF_B_HI + b_dst0, BhG);
        CPASYNC16(sb + OFF_B_HI + b_dst1, BhG + 8);
        CPASYNC16(sb + OFF_B_LO + b_dst0, BlG);
        CPASYNC16(sb + OFF_B_LO + b_dst1, BlG + 8);
        CPCOMMIT();
        uint4 hi0 = {pack_hi(st[0].x, st[0].y), pack_hi(st[0].z, st[0].w),
                     pack_hi(st[1].x, st[1].y), pack_hi(st[1].z, st[1].w)};
        uint4 hi1 = {pack_hi(st[2].x, st[2].y), pack_hi(st[2].z, st[2].w),
                     pack_hi(st[3].x, st[3].y), pack_hi(st[3].z, st[3].w)};
        uint4 lo0 = {pack_lo(st[0].x, st[0].y), pack_lo(st[0].z, st[0].w),
                     pack_lo(st[1].x, st[1].y), pack_lo(st[1].z, st[1].w)};
        uint4 lo1 = {pack_lo(st[2].x, st[2].y), pack_lo(st[2].z, st[2].w),
                     pack_lo(st[3].x, st[3].y), pack_lo(st[3].z, st[3].w)};
        *(uint4*)(smem + OFF_A_HI + a_sts0) = hi0;
        *(uint4*)(smem + OFF_A_HI + a_sts1) = hi1;
        *(uint4*)(smem + OFF_A_LO + a_sts0) = lo0;
        *(uint4*)(smem + OFF_A_LO + a_sts1) = lo1;
    }

    for (int c = 0; c < 16; c++) {
        const uint32_t buf  = sb + (c & 1) * BUF_STRIDE;
        const uint32_t nbuf = sb + ((c + 1) & 1) * BUF_STRIDE;
        CPWAIT0();
        __syncthreads();

        float4 st[4];
        if (c < 15) {
            #pragma unroll
            for (int q = 0; q < 4; q++) st[q] = Ag[(c + 1) * 8 + ahalf * 4 + q];
            CPASYNC16(nbuf + OFF_B_HI + b_dst0, BhG + (c + 1) * 32);
            CPASYNC16(nbuf + OFF_B_HI + b_dst1, BhG + (c + 1) * 32 + 8);
            CPASYNC16(nbuf + OFF_B_LO + b_dst0, BlG + (c + 1) * 32);
            CPASYNC16(nbuf + OFF_B_LO + b_dst1, BlG + (c + 1) * 32 + 8);
            CPCOMMIT();
        }

        // ---- compute chunk c ----
        // Term-major over a pair of p-tiles: same-accumulator reuse distance = 8 MMAs
        // (was 1 -> accumulator RAW stalled the tensor pipe).
        #pragma unroll
        for (int ks = 0; ks < 2; ks++) {
            uint32_t aH[2][4], aL[2][4];
            #pragma unroll
            for (int mt = 0; mt < 2; mt++) {
                LDSM4(aH[mt][0], aH[mt][1], aH[mt][2], aH[mt][3], buf + OFF_A_HI + a_off[mt][ks]);
                LDSM4(aL[mt][0], aL[mt][1], aL[mt][2], aL[mt][3], buf + OFF_A_LO + a_off[mt][ks]);
            }
            #pragma unroll
            for (int pp = 0; pp < 2; pp++) {       // p-pair {2pp, 2pp+1}
                uint32_t bh[2][4], bl[2][4];
                #pragma unroll
                for (int q = 0; q < 2; q++) {
                    LDSM4(bh[q][0], bh[q][1], bh[q][2], bh[q][3],
                          buf + OFF_B_HI + b_off[2 * pp + q][ks]);
                    LDSM4(bl[q][0], bl[q][1], bl[q][2], bl[q][3],
                          buf + OFF_B_LO + b_off[2 * pp + q][ks]);
                }
                // HH x8
                #pragma unroll
                for (int q = 0; q < 2; q++)
                    #pragma unroll
                    for (int mt = 0; mt < 2; mt++) {
                        MMA(d[mt][4 * pp + 2 * q],     aH[mt], bh[q][0], bh[q][1]);
                        MMA(d[mt][4 * pp + 2 * q + 1], aH[mt], bh[q][2], bh[q][3]);
                    }
                // LH x8
                #pragma unroll
                for (int q = 0; q < 2; q++)
                    #pragma unroll
                    for (int mt = 0; mt < 2; mt++) {
                        MMA(d[mt][4 * pp + 2 * q],     aL[mt], bh[q][0], bh[q][1]);
                        MMA(d[mt][4 * pp + 2 * q + 1], aL[mt], bh[q][2], bh[q][3]);
                    }
                // HL x8
                #pragma unroll
                for (int q = 0; q < 2; q++)
                    #pragma unroll
                    for (int mt = 0; mt < 2; mt++) {
                        MMA(d[mt][4 * pp + 2 * q],     aH[mt], bl[q][0], bl[q][1]);
                        MMA(d[mt][4 * pp + 2 * q + 1], aH[mt], bl[q][2], bl[q][3]);
                    }
            }
        }

        if (c < 15) {
            uint4 hi0 = {pack_hi(st[0].x, st[0].y), pack_hi(st[0].z, st[0].w),
                         pack_hi(st[1].x, st[1].y), pack_hi(st[1].z, st[1].w)};
            uint4 hi1 = {pack_hi(st[2].x, st[2].y), pack_hi(st[2].z, st[2].w),
                         pack_hi(st[3].x, st[3].y), pack_hi(st[3].z, st[3].w)};
            uint4 lo0 = {pack_lo(st[0].x, st[0].y), pack_lo(st[0].z, st[0].w),
                         pack_lo(st[1].x, st[1].y), pack_lo(st[1].z, st[1].w)};
            uint4 lo1 = {pack_lo(st[2].x, st[2].y), pack_lo(st[2].z, st[2].w),
                         pack_lo(st[3].x, st[3].y), pack_lo(st[3].z, st[3].w)};
            char* nb = smem + ((c + 1) & 1) * BUF_STRIDE;
            *(uint4*)(nb + OFF_A_HI + a_sts0) = hi0;
            *(uint4*)(nb + OFF_A_HI + a_sts1) = hi1;
            *(uint4*)(nb + OFF_A_LO + a_sts0) = lo0;
            *(uint4*)(nb + OFF_A_LO + a_sts1) = lo1;
        }
    }

    // ---- epilogue ----
    const float* bt = (EDGE ? bias1 : (mat ? bias2 : bias1)) + (size_t)t * HDIM;
    const int c2 = (lane & 3) * 2, gr = lane >> 2;
    float2 bv[8];
    #pragma unroll
    for (int n8 = 0; n8 < 8; n8++)
        bv[n8] = *(const float2*)(bt + cx + wn * 64 + n8 * 8 + c2);

    if (!EDGE) {
        float* C = mat ? C2 : C1;
        #pragma unroll
        for (int mt = 0; mt < 2; mt++) {
            const int r0 = ry + wm * 32 + mt * 16 + gr;
            float* p0 = C + (size_t)r0 * HDIM + cx + wn * 64 + c2;
            float* p1 = p0 + (size_t)8 * HDIM;
            #pragma unroll
            for (int n8 = 0; n8 < 8; n8++) {
                *(float2*)(p0 + n8 * 8) = make_float2(d[mt][n8][0] + bv[n8].x,
                                                      d[mt][n8][1] + bv[n8].y);
                *(float2*)(p1 + n8 * 8) = make_float2(d[mt][n8][2] + bv[n8].x,
                                                      d[mt][n8][3] + bv[n8].y);
            }
        }
    } else {
        #pragma unroll
        for (int mt = 0; mt < 2; mt++) {
            const int e0 = ry + wm * 32 + mt * 16 + gr;
            const int2 ea = ((const int2*)edges)[e0];
            const int2 eb = ((const int2*)edges)[e0 + 8];
            const float* wa = g_w2f + (size_t)ea.y * HDIM + cx + wn * 64 + c2;
            const float* wb = g_w2f + (size_t)eb.y * HDIM + cx + wn * 64 + c2;
            float* oa = out + (size_t)ea.x * HDIM + cx + wn * 64 + c2;
            float* ob = out + (size_t)eb.x * HDIM + cx + wn * 64 + c2;
            #pragma unroll
            for (int n8 = 0; n8 < 8; n8++) {
                float2 ga = *(const float2*)(wa + n8 * 8);
                float2 gb = *(const float2*)(wb + n8 * 8);
                atomicAdd(oa + n8 * 8 + 0, d[mt][n8][0] + bv[n8].x + ga.x);
                atomicAdd(oa + n8 * 8 + 1, d[mt][n8][1] + bv[n8].y + ga.y);
                atomicAdd(ob + n8 * 8 + 0, d[mt][n8][2] + bv[n8].x + gb.x);
                atomicAdd(ob + n8 * 8 + 1, d[mt][n8][3] + bv[n8].y + gb.y);
            }
        }
    }
}

extern "C" void kernel_launch(void* const* d_in, const int* in_sizes, int n_in,
                              void* d_out, int out_size)
{
    const float* X  = (const float*)d_in[0];
    const float* E0 = (const float*)d_in[1];
    const float* E1 = (const float*)d_in[2];
    const float* W1 = (const float*)d_in[3];
    const float* b1 = (const float*)d_in[4];
    const float* W2 = (const float*)d_in[5];
    const float* b2 = (const float*)d_in[6];
    const float* W5 = (const float*)d_in[11];
    const float* b5 = (const float*)d_in[12];
    const int* edges0 = (const int*)d_in[13];   // JAX x64-disabled: int32 pairs
    const int* edges1 = (const int*)d_in[14];
    float* out = (float*)d_out;

    float* w2f = nullptr;
    cudaGetSymbolAddress((void**)&w2f, g_w2f);

    cudaFuncSetAttribute(mma_gemm<false>, cudaFuncAttributeMaxDynamicSharedMemorySize, SMEM_TOTAL);
    cudaFuncSetAttribute(mma_gemm<true>,  cudaFuncAttributeMaxDynamicSharedMemorySize, SMEM_TOTAL);

    prep_weights<<<dim3(16, 16, 6), 256>>>(W1, W2, W5);
    // Fused: out = X@W1[t] + b1[t]  AND  w2f = X@W2[t] + b2[t]  (X streamed once)
    mma_gemm<false><<<dim3(8, 1024), 256, SMEM_TOTAL>>>(X, 0, b1, b2, out, w2f,
                                                        nullptr, nullptr);
    // out[src] += (E@W5[t] + b5[t]) + w2f[dst]   (softmax over singleton = 1)
    mma_gemm<true><<<dim3(4, 512), 256, SMEM_TOTAL>>>(E0, 0, b5, nullptr, nullptr, nullptr,
                                                      edges0, out);
    mma_gemm<true><<<dim3(4, 512), 256, SMEM_TOTAL>>>(E1, 1, b5, nullptr, nullptr, nullptr,
                                                      edges1, out);
}

// round 8
// speedup vs baseline: 2.9688x; 1.2889x over previous
#include <cuda_runtime.h>
#include <cuda_fp16.h>
#include <cstdint>

#define NROWS 131072
#define HALFN 65536
#define DDIM  512
#define HDIM  512
#define EPTN  65536

__device__ float g_w2f[(size_t)NROWS * HDIM];
__device__ __half g_wh[6u * 512 * 512];   // [z=mat*2+t][n][k] fp16

// SMEM per buffer: A_HI 8K | A_LO 8K | B_HI 8K = 24K, x2 buffers
#define BUF_STRIDE 24576
#define OFF_A_HI 0
#define OFF_A_LO 8192
#define OFF_B_HI 16384
#define SMEM_TOTAL (2 * BUF_STRIDE)

#define SWZ64(o) ((o) ^ (((o) >> 3) & 0x30))

__device__ __forceinline__ uint32_t smem_u32(const void* p) {
    uint32_t a;
    asm("{ .reg .u64 t; cvta.to.shared.u64 t, %1; cvt.u32.u64 %0, t; }" : "=r"(a) : "l"(p));
    return a;
}
#define CPASYNC16(dst, src) asm volatile("cp.async.cg.shared.global [%0], [%1], 16;" :: "r"(dst), "l"(src))
#define CPCOMMIT() asm volatile("cp.async.commit_group;" ::: "memory")
#define CPWAIT0()  asm volatile("cp.async.wait_group 0;" ::: "memory")
#define LDSM4(r0, r1, r2, r3, ad) \
    asm volatile("ldmatrix.sync.aligned.m8n8.x4.shared.b16 {%0,%1,%2,%3}, [%4];" \
        : "=r"(r0), "=r"(r1), "=r"(r2), "=r"(r3) : "r"(ad))
#define MMA(d, a, b0, b1) \
    asm volatile("mma.sync.aligned.m16n8k16.row.col.f32.f16.f16.f32 " \
        "{%0,%1,%2,%3}, {%4,%5,%6,%7}, {%8,%9}, {%0,%1,%2,%3};" \
        : "+f"((d)[0]), "+f"((d)[1]), "+f"((d)[2]), "+f"((d)[3]) \
        : "r"((a)[0]), "r"((a)[1]), "r"((a)[2]), "r"((a)[3]), "r"(b0), "r"(b1))

__device__ __forceinline__ uint32_t pack_hi(float a, float b) {
    __half2 h = __floats2half2_rn(a, b);
    return *(uint32_t*)&h;
}
__device__ __forceinline__ uint32_t pack_lo(float a, float b) {
    float ra = a - __half2float(__float2half_rn(a));
    float rb = b - __half2float(__float2half_rn(b));
    __half2 h = __floats2half2_rn(ra, rb);
    return *(uint32_t*)&h;
}

// Transpose W1/W2/W5 into [z][n][k] fp16
__global__ void prep_weights(const float* __restrict__ W1, const float* __restrict__ W2,
                             const float* __restrict__ W5) {
    __shared__ float tile[32][33];
    int z = blockIdx.z, mat = z >> 1, t = z & 1;
    const float* W = (mat == 0 ? W1 : mat == 1 ? W2 : W5) + (size_t)t * 512 * 512;
    int n0 = blockIdx.x * 32, k0 = blockIdx.y * 32;
    int lx = threadIdx.x & 31, ly = threadIdx.x >> 5;
    #pragma unroll
    for (int i = 0; i < 32; i += 8)
        tile[ly + i][lx] = W[(size_t)(k0 + ly + i) * 512 + n0 + lx];
    __syncthreads();
    size_t base = ((size_t)z * 512 + n0) * 512 + k0;
    #pragma unroll
    for (int i = 0; i < 32; i += 8)
        g_wh[base + (size_t)(ly + i) * 512 + lx] = __float2half_rn(tile[lx][ly + i]);
}

// EDGE=false: fused dual-proj. blockIdx.x in [0,8): mat = bx>>2 (0->W1/out, 1->W2/w2f).
// EDGE=true : edge GEMM + gather/scatter epilogue (mat=2).
template<bool EDGE>
__global__ __launch_bounds__(256, 2)
void mma_gemm(const float* __restrict__ A, int tparam,
              const float* __restrict__ bias1, const float* __restrict__ bias2,
              float* __restrict__ C1, float* __restrict__ C2,
              const int* __restrict__ edges, float* __restrict__ out)
{
    extern __shared__ char smem[];
    const uint32_t sb = smem_u32(smem);
    const int tid = threadIdx.x, wid = tid >> 5, lane = tid & 31;
    const int bx = blockIdx.x;
    const int ry = blockIdx.y * 128;
    const int cx = (EDGE ? bx : (bx & 3)) * 128;
    const int mat = EDGE ? 2 : (bx >> 2);
    const int t = EDGE ? tparam : (ry >= HALFN ? 1 : 0);
    const int z = mat * 2 + t;
    const int wm = wid & 3, wn = wid >> 2;   // warp tile (wm*32, wn*64)

    // ---- fill mappings ----
    const int arow = tid >> 1, ahalf = tid & 1;      // A: 2 thr/row, 16 floats each
    const float4* Ag = (const float4*)(A + (size_t)(ry + arow) * DDIM);
    const int brow = tid >> 1, bhalf = tid & 1;      // B: 2 thr/row, 16 fp16 each
    const __half* BhG = g_wh + ((size_t)z * 512 + cx + brow) * 512 + bhalf * 16;
    const uint32_t a_sts0 = SWZ64(arow * 64 + ahalf * 32);
    const uint32_t a_sts1 = SWZ64(arow * 64 + ahalf * 32 + 16);
    const uint32_t b_dst0 = SWZ64(brow * 64 + bhalf * 32);
    const uint32_t b_dst1 = SWZ64(brow * 64 + bhalf * 32 + 16);

    // ---- ldmatrix per-lane offsets (chunk-independent) ----
    uint32_t a_off[2][2];
    #pragma unroll
    for (int mt = 0; mt < 2; mt++)
        #pragma unroll
        for (int ks = 0; ks < 2; ks++)
            a_off[mt][ks] = SWZ64((wm * 32 + mt * 16 + (lane & 15)) * 64 +
                                  ks * 32 + (lane >> 4) * 16);
    uint32_t b_off[4][2];
    #pragma unroll
    for (int p = 0; p < 4; p++)
        #pragma unroll
        for (int ks = 0; ks < 2; ks++)
            b_off[p][ks] = SWZ64((wn * 64 + p * 16 + (lane & 7) + ((lane & 16) ? 8 : 0)) * 64 +
                                 ks * 32 + ((lane & 8) ? 16 : 0));

    float d[2][8][4];
    #pragma unroll
    for (int i = 0; i < 2; i++)
        #pragma unroll
        for (int j = 0; j < 8; j++)
            #pragma unroll
            for (int q = 0; q < 4; q++) d[i][j][q] = 0.f;

    // ---- prologue: fill buffer 0 (chunk 0) ----
    {
        float4 st[4];
        #pragma unroll
        for (int q = 0; q < 4; q++) st[q] = Ag[ahalf * 4 + q];
        CPASYNC16(sb + OFF_B_HI + b_dst0, BhG);
        CPASYNC16(sb + OFF_B_HI + b_dst1, BhG + 8);
        CPCOMMIT();
        uint4 hi0 = {pack_hi(st[0].x, st[0].y), pack_hi(st[0].z, st[0].w),
                     pack_hi(st[1].x, st[1].y), pack_hi(st[1].z, st[1].w)};
        uint4 hi1 = {pack_hi(st[2].x, st[2].y), pack_hi(st[2].z, st[2].w),
                     pack_hi(st[3].x, st[3].y), pack_hi(st[3].z, st[3].w)};
        uint4 lo0 = {pack_lo(st[0].x, st[0].y), pack_lo(st[0].z, st[0].w),
                     pack_lo(st[1].x, st[1].y), pack_lo(st[1].z, st[1].w)};
        uint4 lo1 = {pack_lo(st[2].x, st[2].y), pack_lo(st[2].z, st[2].w),
                     pack_lo(st[3].x, st[3].y), pack_lo(st[3].z, st[3].w)};
        *(uint4*)(smem + OFF_A_HI + a_sts0) = hi0;
        *(uint4*)(smem + OFF_A_HI + a_sts1) = hi1;
        *(uint4*)(smem + OFF_A_LO + a_sts0) = lo0;
        *(uint4*)(smem + OFF_A_LO + a_sts1) = lo1;
    }

    for (int c = 0; c < 16; c++) {
        const uint32_t buf  = sb + (c & 1) * BUF_STRIDE;
        const uint32_t nbuf = sb + ((c + 1) & 1) * BUF_STRIDE;
        CPWAIT0();
        __syncthreads();

        float4 st[4];
        if (c < 15) {
            #pragma unroll
            for (int q = 0; q < 4; q++) st[q] = Ag[(c + 1) * 8 + ahalf * 4 + q];
            CPASYNC16(nbuf + OFF_B_HI + b_dst0, BhG + (c + 1) * 32);
            CPASYNC16(nbuf + OFF_B_HI + b_dst1, BhG + (c + 1) * 32 + 8);
            CPCOMMIT();
        }

        // ---- compute chunk c ----
        // fp16 2-term split: D = Ah*Bh + Al*Bh. Term-major over all 4 p-tiles:
        // same-accumulator reuse distance = 16 MMAs.
        #pragma unroll
        for (int ks = 0; ks < 2; ks++) {
            uint32_t aH[2][4], aL[2][4], bh[4][4];
            #pragma unroll
            for (int mt = 0; mt < 2; mt++) {
                LDSM4(aH[mt][0], aH[mt][1], aH[mt][2], aH[mt][3], buf + OFF_A_HI + a_off[mt][ks]);
                LDSM4(aL[mt][0], aL[mt][1], aL[mt][2], aL[mt][3], buf + OFF_A_LO + a_off[mt][ks]);
            }
            #pragma unroll
            for (int p = 0; p < 4; p++)
                LDSM4(bh[p][0], bh[p][1], bh[p][2], bh[p][3], buf + OFF_B_HI + b_off[p][ks]);
            #pragma unroll
            for (int p = 0; p < 4; p++)
                #pragma unroll
                for (int mt = 0; mt < 2; mt++) {
                    MMA(d[mt][2 * p],     aH[mt], bh[p][0], bh[p][1]);
                    MMA(d[mt][2 * p + 1], aH[mt], bh[p][2], bh[p][3]);
                }
            #pragma unroll
            for (int p = 0; p < 4; p++)
                #pragma unroll
                for (int mt = 0; mt < 2; mt++) {
                    MMA(d[mt][2 * p],     aL[mt], bh[p][0], bh[p][1]);
                    MMA(d[mt][2 * p + 1], aL[mt], bh[p][2], bh[p][3]);
                }
        }

        if (c < 15) {
            uint4 hi0 = {pack_hi(st[0].x, st[0].y), pack_hi(st[0].z, st[0].w),
                         pack_hi(st[1].x, st[1].y), pack_hi(st[1].z, st[1].w)};
            uint4 hi1 = {pack_hi(st[2].x, st[2].y), pack_hi(st[2].z, st[2].w),
                         pack_hi(st[3].x, st[3].y), pack_hi(st[3].z, st[3].w)};
            uint4 lo0 = {pack_lo(st[0].x, st[0].y), pack_lo(st[0].z, st[0].w),
                         pack_lo(st[1].x, st[1].y), pack_lo(st[1].z, st[1].w)};
            uint4 lo1 = {pack_lo(st[2].x, st[2].y), pack_lo(st[2].z, st[2].w),
                         pack_lo(st[3].x, st[3].y), pack_lo(st[3].z, st[3].w)};
            char* nb = smem + ((c + 1) & 1) * BUF_STRIDE;
            *(uint4*)(nb + OFF_A_HI + a_sts0) = hi0;
            *(uint4*)(nb + OFF_A_HI + a_sts1) = hi1;
            *(uint4*)(nb + OFF_A_LO + a_sts0) = lo0;
            *(uint4*)(nb + OFF_A_LO + a_sts1) = lo1;
        }
    }

    // ---- epilogue ----
    const float* bt = (EDGE ? bias1 : (mat ? bias2 : bias1)) + (size_t)t * HDIM;
    const int c2 = (lane & 3) * 2, gr = lane >> 2;
    float2 bv[8];
    #pragma unroll
    for (int n8 = 0; n8 < 8; n8++)
        bv[n8] = *(const float2*)(bt + cx + wn * 64 + n8 * 8 + c2);

    if (!EDGE) {
        float* C = mat ? C2 : C1;
        #pragma unroll
        for (int mt = 0; mt < 2; mt++) {
            const int r0 = ry + wm * 32 + mt * 16 + gr;
            float* p0 = C + (size_t)r0 * HDIM + cx + wn * 64 + c2;
            float* p1 = p0 + (size_t)8 * HDIM;
            #pragma unroll
            for (int n8 = 0; n8 < 8; n8++) {
                *(float2*)(p0 + n8 * 8) = make_float2(d[mt][n8][0] + bv[n8].x,
                                                      d[mt][n8][1] + bv[n8].y);
                *(float2*)(p1 + n8 * 8) = make_float2(d[mt][n8][2] + bv[n8].x,
                                                      d[mt][n8][3] + bv[n8].y);
            }
        }
    } else {
        #pragma unroll
        for (int mt = 0; mt < 2; mt++) {
            const int e0 = ry + wm * 32 + mt * 16 + gr;
            const int2 ea = ((const int2*)edges)[e0];
            const int2 eb = ((const int2*)edges)[e0 + 8];
            const float* wa = g_w2f + (size_t)ea.y * HDIM + cx + wn * 64 + c2;
            const float* wb = g_w2f + (size_t)eb.y * HDIM + cx + wn * 64 + c2;
            float* oa = out + (size_t)ea.x * HDIM + cx + wn * 64 + c2;
            float* ob = out + (size_t)eb.x * HDIM + cx + wn * 64 + c2;
            #pragma unroll
            for (int n8 = 0; n8 < 8; n8++) {
                float2 ga = *(const float2*)(wa + n8 * 8);
                float2 gb = *(const float2*)(wb + n8 * 8);
                atomicAdd(oa + n8 * 8 + 0, d[mt][n8][0] + bv[n8].x + ga.x);
                atomicAdd(oa + n8 * 8 + 1, d[mt][n8][1] + bv[n8].y + ga.y);
                atomicAdd(ob + n8 * 8 + 0, d[mt][n8][2] + bv[n8].x + gb.x);
                atomicAdd(ob + n8 * 8 + 1, d[mt][n8][3] + bv[n8].y + gb.y);
            }
        }
    }
}

extern "C" void kernel_launch(void* const* d_in, const int* in_sizes, int n_in,
                              void* d_out, int out_size)
{
    const float* X  = (const float*)d_in[0];
    const float* E0 = (const float*)d_in[1];
    const float* E1 = (const float*)d_in[2];
    const float* W1 = (const float*)d_in[3];
    const float* b1 = (const float*)d_in[4];
    const float* W2 = (const float*)d_in[5];
    const float* b2 = (const float*)d_in[6];
    const float* W5 = (const float*)d_in[11];
    const float* b5 = (const float*)d_in[12];
    const int* edges0 = (const int*)d_in[13];   // JAX x64-disabled: int32 pairs
    const int* edges1 = (const int*)d_in[14];
    float* out = (float*)d_out;

    float* w2f = nullptr;
    cudaGetSymbolAddress((void**)&w2f, g_w2f);

    cudaFuncSetAttribute(mma_gemm<false>, cudaFuncAttributeMaxDynamicSharedMemorySize, SMEM_TOTAL);
    cudaFuncSetAttribute(mma_gemm<true>,  cudaFuncAttributeMaxDynamicSharedMemorySize, SMEM_TOTAL);

    prep_weights<<<dim3(16, 16, 6), 256>>>(W1, W2, W5);
    // Fused: out = X@W1[t] + b1[t]  AND  w2f = X@W2[t] + b2[t]  (X streamed once)
    mma_gemm<false><<<dim3(8, 1024), 256, SMEM_TOTAL>>>(X, 0, b1, b2, out, w2f,
                                                        nullptr, nullptr);
    // out[src] += (E@W5[t] + b5[t]) + w2f[dst]   (softmax over singleton = 1)
    mma_gemm<true><<<dim3(4, 512), 256, SMEM_TOTAL>>>(E0, 0, b5, nullptr, nullptr, nullptr,
                                                      edges0, out);
    mma_gemm<true><<<dim3(4, 512), 256, SMEM_TOTAL>>>(E1, 1, b5, nullptr, nullptr, nullptr,
                                                      edges1, out);
}

// round 9
// speedup vs baseline: 3.2056x; 1.0798x over previous
#include <cuda_runtime.h>
#include <cuda_fp16.h>
#include <cstdint>

#define NROWS 131072
#define HALFN 65536
#define DDIM  512
#define HDIM  512
#define EPTN  65536

__device__ __half g_w2fh[(size_t)NROWS * HDIM];   // w2f = X@W2+b2, fp16 (128 MB)
__device__ __half g_wh[6u * 512 * 512];           // [z=mat*2+t][n][k] fp16 weights

// SMEM per buffer: A_HI 8K | A_LO 8K | B_HI 8K = 24K, x2 buffers
#define BUF_STRIDE 24576
#define OFF_A_HI 0
#define OFF_A_LO 8192
#define OFF_B_HI 16384
#define SMEM_TOTAL (2 * BUF_STRIDE)

#define SWZ64(o) ((o) ^ (((o) >> 3) & 0x30))

__device__ __forceinline__ uint32_t smem_u32(const void* p) {
    uint32_t a;
    asm("{ .reg .u64 t; cvta.to.shared.u64 t, %1; cvt.u32.u64 %0, t; }" : "=r"(a) : "l"(p));
    return a;
}
#define CPASYNC16(dst, src) asm volatile("cp.async.cg.shared.global [%0], [%1], 16;" :: "r"(dst), "l"(src))
#define CPCOMMIT() asm volatile("cp.async.commit_group;" ::: "memory")
#define CPWAIT0()  asm volatile("cp.async.wait_group 0;" ::: "memory")
#define LDSM4(r0, r1, r2, r3, ad) \
    asm volatile("ldmatrix.sync.aligned.m8n8.x4.shared.b16 {%0,%1,%2,%3}, [%4];" \
        : "=r"(r0), "=r"(r1), "=r"(r2), "=r"(r3) : "r"(ad))
#define MMA(d, a, b0, b1) \
    asm volatile("mma.sync.aligned.m16n8k16.row.col.f32.f16.f16.f32 " \
        "{%0,%1,%2,%3}, {%4,%5,%6,%7}, {%8,%9}, {%0,%1,%2,%3};" \
        : "+f"((d)[0]), "+f"((d)[1]), "+f"((d)[2]), "+f"((d)[3]) \
        : "r"((a)[0]), "r"((a)[1]), "r"((a)[2]), "r"((a)[3]), "r"(b0), "r"(b1))
#define REDV2(p, x, y) \
    asm volatile("red.global.add.v2.f32 [%0], {%1, %2};" :: "l"(p), "f"(x), "f"(y) : "memory")

__device__ __forceinline__ uint32_t pack_hi(float a, float b) {
    __half2 h = __floats2half2_rn(a, b);
    return *(uint32_t*)&h;
}
__device__ __forceinline__ uint32_t pack_lo(float a, float b) {
    float ra = a - __half2float(__float2half_rn(a));
    float rb = b - __half2float(__float2half_rn(b));
    __half2 h = __floats2half2_rn(ra, rb);
    return *(uint32_t*)&h;
}

// Transpose W1/W2/W5 into [z][n][k] fp16
__global__ void prep_weights(const float* __restrict__ W1, const float* __restrict__ W2,
                             const float* __restrict__ W5) {
    __shared__ float tile[32][33];
    int z = blockIdx.z, mat = z >> 1, t = z & 1;
    const float* W = (mat == 0 ? W1 : mat == 1 ? W2 : W5) + (size_t)t * 512 * 512;
    int n0 = blockIdx.x * 32, k0 = blockIdx.y * 32;
    int lx = threadIdx.x & 31, ly = threadIdx.x >> 5;
    #pragma unroll
    for (int i = 0; i < 32; i += 8)
        tile[ly + i][lx] = W[(size_t)(k0 + ly + i) * 512 + n0 + lx];
    __syncthreads();
    size_t base = ((size_t)z * 512 + n0) * 512 + k0;
    #pragma unroll
    for (int i = 0; i < 32; i += 8)
        g_wh[base + (size_t)(ly + i) * 512 + lx] = __float2half_rn(tile[lx][ly + i]);
}

// EDGE=false: fused dual-proj. bx in [0,8): mat = bx>>2 (0 -> W1/out(f32), 1 -> W2/w2f(f16)).
// EDGE=true : merged edge sets. by>>9 = set; GEMM(E_set@W5[set]) + gather/scatter epilogue.
template<bool EDGE>
__global__ __launch_bounds__(256, 2)
void mma_gemm(const float* __restrict__ A0, const float* __restrict__ A1,
              const float* __restrict__ bias1, const float* __restrict__ bias2,
              float* __restrict__ out,
              const int* __restrict__ e0, const int* __restrict__ e1)
{
    extern __shared__ char smem[];
    const uint32_t sb = smem_u32(smem);
    const int tid = threadIdx.x, wid = tid >> 5, lane = tid & 31;
    const int bx = blockIdx.x, by = blockIdx.y;
    const int set = EDGE ? (by >> 9) : 0;
    const int ry = (EDGE ? (by & 511) : by) * 128;
    const int cx = (EDGE ? bx : (bx & 3)) * 128;
    const int mat = EDGE ? 2 : (bx >> 2);
    const int t = EDGE ? set : (ry >= HALFN ? 1 : 0);
    const int z = mat * 2 + t;
    const float* A = (EDGE && set) ? A1 : A0;
    const int* edges = EDGE ? (set ? e1 : e0) : nullptr;
    const int wm = wid & 3, wn = wid >> 2;   // warp tile (wm*32, wn*64)

    // ---- fill mappings ----
    const int arow = tid >> 1, ahalf = tid & 1;      // A: 2 thr/row, 16 floats each
    const float4* Ag = (const float4*)(A + (size_t)(ry + arow) * DDIM);
    const int brow = tid >> 1, bhalf = tid & 1;      // B: 2 thr/row, 16 fp16 each
    const __half* BhG = g_wh + ((size_t)z * 512 + cx + brow) * 512 + bhalf * 16;
    const uint32_t a_sts0 = SWZ64(arow * 64 + ahalf * 32);
    const uint32_t a_sts1 = SWZ64(arow * 64 + ahalf * 32 + 16);
    const uint32_t b_dst0 = SWZ64(brow * 64 + bhalf * 32);
    const uint32_t b_dst1 = SWZ64(brow * 64 + bhalf * 32 + 16);

    // ---- ldmatrix per-lane offsets (chunk-independent) ----
    uint32_t a_off[2][2];
    #pragma unroll
    for (int mt = 0; mt < 2; mt++)
        #pragma unroll
        for (int ks = 0; ks < 2; ks++)
            a_off[mt][ks] = SWZ64((wm * 32 + mt * 16 + (lane & 15)) * 64 +
                                  ks * 32 + (lane >> 4) * 16);
    uint32_t b_off[4][2];
    #pragma unroll
    for (int p = 0; p < 4; p++)
        #pragma unroll
        for (int ks = 0; ks < 2; ks++)
            b_off[p][ks] = SWZ64((wn * 64 + p * 16 + (lane & 7) + ((lane & 16) ? 8 : 0)) * 64 +
                                 ks * 32 + ((lane & 8) ? 16 : 0));

    float d[2][8][4];
    #pragma unroll
    for (int i = 0; i < 2; i++)
        #pragma unroll
        for (int j = 0; j < 8; j++)
            #pragma unroll
            for (int q = 0; q < 4; q++) d[i][j][q] = 0.f;

    // ---- prologue: fill buffer 0 (chunk 0) ----
    {
        float4 st[4];
        #pragma unroll
        for (int q = 0; q < 4; q++) st[q] = Ag[ahalf * 4 + q];
        CPASYNC16(sb + OFF_B_HI + b_dst0, BhG);
        CPASYNC16(sb + OFF_B_HI + b_dst1, BhG + 8);
        CPCOMMIT();
        uint4 hi0 = {pack_hi(st[0].x, st[0].y), pack_hi(st[0].z, st[0].w),
                     pack_hi(st[1].x, st[1].y), pack_hi(st[1].z, st[1].w)};
        uint4 hi1 = {pack_hi(st[2].x, st[2].y), pack_hi(st[2].z, st[2].w),
                     pack_hi(st[3].x, st[3].y), pack_hi(st[3].z, st[3].w)};
        uint4 lo0 = {pack_lo(st[0].x, st[0].y), pack_lo(st[0].z, st[0].w),
                     pack_lo(st[1].x, st[1].y), pack_lo(st[1].z, st[1].w)};
        uint4 lo1 = {pack_lo(st[2].x, st[2].y), pack_lo(st[2].z, st[2].w),
                     pack_lo(st[3].x, st[3].y), pack_lo(st[3].z, st[3].w)};
        *(uint4*)(smem + OFF_A_HI + a_sts0) = hi0;
        *(uint4*)(smem + OFF_A_HI + a_sts1) = hi1;
        *(uint4*)(smem + OFF_A_LO + a_sts0) = lo0;
        *(uint4*)(smem + OFF_A_LO + a_sts1) = lo1;
    }

    for (int c = 0; c < 16; c++) {
        const uint32_t buf  = sb + (c & 1) * BUF_STRIDE;
        const uint32_t nbuf = sb + ((c + 1) & 1) * BUF_STRIDE;
        CPWAIT0();
        __syncthreads();

        float4 st[4];
        if (c < 15) {
            #pragma unroll
            for (int q = 0; q < 4; q++) st[q] = Ag[(c + 1) * 8 + ahalf * 4 + q];
            CPASYNC16(nbuf + OFF_B_HI + b_dst0, BhG + (c + 1) * 32);
            CPASYNC16(nbuf + OFF_B_HI + b_dst1, BhG + (c + 1) * 32 + 8);
            CPCOMMIT();
        }

        // ---- compute chunk c: D = Ah*Bh + Al*Bh, term-major ----
        #pragma unroll
        for (int ks = 0; ks < 2; ks++) {
            uint32_t aH[2][4], aL[2][4], bh[4][4];
            #pragma unroll
            for (int mt = 0; mt < 2; mt++) {
                LDSM4(aH[mt][0], aH[mt][1], aH[mt][2], aH[mt][3], buf + OFF_A_HI + a_off[mt][ks]);
                LDSM4(aL[mt][0], aL[mt][1], aL[mt][2], aL[mt][3], buf + OFF_A_LO + a_off[mt][ks]);
            }
            #pragma unroll
            for (int p = 0; p < 4; p++)
                LDSM4(bh[p][0], bh[p][1], bh[p][2], bh[p][3], buf + OFF_B_HI + b_off[p][ks]);
            #pragma unroll
            for (int p = 0; p < 4; p++)
                #pragma unroll
                for (int mt = 0; mt < 2; mt++) {
                    MMA(d[mt][2 * p],     aH[mt], bh[p][0], bh[p][1]);
                    MMA(d[mt][2 * p + 1], aH[mt], bh[p][2], bh[p][3]);
                }
            #pragma unroll
            for (int p = 0; p < 4; p++)
                #pragma unroll
                for (int mt = 0; mt < 2; mt++) {
                    MMA(d[mt][2 * p],     aL[mt], bh[p][0], bh[p][1]);
                    MMA(d[mt][2 * p + 1], aL[mt], bh[p][2], bh[p][3]);
                }
        }

        if (c < 15) {
            uint4 hi0 = {pack_hi(st[0].x, st[0].y), pack_hi(st[0].z, st[0].w),
                         pack_hi(st[1].x, st[1].y), pack_hi(st[1].z, st[1].w)};
            uint4 hi1 = {pack_hi(st[2].x, st[2].y), pack_hi(st[2].z, st[2].w),
                         pack_hi(st[3].x, st[3].y), pack_hi(st[3].z, st[3].w)};
            uint4 lo0 = {pack_lo(st[0].x, st[0].y), pack_lo(st[0].z, st[0].w),
                         pack_lo(st[1].x, st[1].y), pack_lo(st[1].z, st[1].w)};
            uint4 lo1 = {pack_lo(st[2].x, st[2].y), pack_lo(st[2].z, st[2].w),
                         pack_lo(st[3].x, st[3].y), pack_lo(st[3].z, st[3].w)};
            char* nb = smem + ((c + 1) & 1) * BUF_STRIDE;
            *(uint4*)(nb + OFF_A_HI + a_sts0) = hi0;
            *(uint4*)(nb + OFF_A_HI + a_sts1) = hi1;
            *(uint4*)(nb + OFF_A_LO + a_sts0) = lo0;
            *(uint4*)(nb + OFF_A_LO + a_sts1) = lo1;
        }
    }

    // ---- epilogue ----
    const float* bt = (EDGE ? bias1 : (mat ? bias2 : bias1)) + (size_t)t * HDIM;
    const int c2 = (lane & 3) * 2, gr = lane >> 2;
    const int colw = cx + wn * 64 + c2;
    float2 bv[8];
    #pragma unroll
    for (int n8 = 0; n8 < 8; n8++)
        bv[n8] = *(const float2*)(bt + colw + n8 * 8);

    if (!EDGE) {
        #pragma unroll
        for (int mt = 0; mt < 2; mt++) {
            const int r0 = ry + wm * 32 + mt * 16 + gr;
            if (mat == 0) {
                float* p0 = out + (size_t)r0 * HDIM + colw;
                float* p1 = p0 + (size_t)8 * HDIM;
                #pragma unroll
                for (int n8 = 0; n8 < 8; n8++) {
                    *(float2*)(p0 + n8 * 8) = make_float2(d[mt][n8][0] + bv[n8].x,
                                                          d[mt][n8][1] + bv[n8].y);
                    *(float2*)(p1 + n8 * 8) = make_float2(d[mt][n8][2] + bv[n8].x,
                                                          d[mt][n8][3] + bv[n8].y);
                }
            } else {
                __half* p0 = g_w2fh + (size_t)r0 * HDIM + colw;
                __half* p1 = p0 + (size_t)8 * HDIM;
                #pragma unroll
                for (int n8 = 0; n8 < 8; n8++) {
                    *(__half2*)(p0 + n8 * 8) = __floats2half2_rn(d[mt][n8][0] + bv[n8].x,
                                                                 d[mt][n8][1] + bv[n8].y);
                    *(__half2*)(p1 + n8 * 8) = __floats2half2_rn(d[mt][n8][2] + bv[n8].x,
                                                                 d[mt][n8][3] + bv[n8].y);
                }
            }
        }
    } else {
        #pragma unroll
        for (int mt = 0; mt < 2; mt++) {
            const int e0i = ry + wm * 32 + mt * 16 + gr;
            const int2 ea = ((const int2*)edges)[e0i];
            const int2 eb = ((const int2*)edges)[e0i + 8];
            const __half* wa = g_w2fh + (size_t)ea.y * HDIM + colw;
            const __half* wb = g_w2fh + (size_t)eb.y * HDIM + colw;
            float* oa = out + (size_t)ea.x * HDIM + colw;
            float* ob = out + (size_t)eb.x * HDIM + colw;
            #pragma unroll
            for (int n8 = 0; n8 < 8; n8++) {
                float2 ga = __half22float2(*(const __half2*)(wa + n8 * 8));
                float2 gb = __half22float2(*(const __half2*)(wb + n8 * 8));
                REDV2(oa + n8 * 8, d[mt][n8][0] + bv[n8].x + ga.x,
                                   d[mt][n8][1] + bv[n8].y + ga.y);
                REDV2(ob + n8 * 8, d[mt][n8][2] + bv[n8].x + gb.x,
                                   d[mt][n8][3] + bv[n8].y + gb.y);
            }
        }
    }
}

extern "C" void kernel_launch(void* const* d_in, const int* in_sizes, int n_in,
                              void* d_out, int out_size)
{
    const float* X  = (const float*)d_in[0];
    const float* E0 = (const float*)d_in[1];
    const float* E1 = (const float*)d_in[2];
    const float* W1 = (const float*)d_in[3];
    const float* b1 = (const float*)d_in[4];
    const float* W2 = (const float*)d_in[5];
    const float* b2 = (const float*)d_in[6];
    const float* W5 = (const float*)d_in[11];
    const float* b5 = (const float*)d_in[12];
    const int* edges0 = (const int*)d_in[13];   // JAX x64-disabled: int32 pairs
    const int* edges1 = (const int*)d_in[14];
    float* out = (float*)d_out;

    cudaFuncSetAttribute(mma_gemm<false>, cudaFuncAttributeMaxDynamicSharedMemorySize, SMEM_TOTAL);
    cudaFuncSetAttribute(mma_gemm<true>,  cudaFuncAttributeMaxDynamicSharedMemorySize, SMEM_TOTAL);

    prep_weights<<<dim3(16, 16, 6), 256>>>(W1, W2, W5);
    // Fused: out = X@W1[t] + b1[t]  AND  w2f(fp16) = X@W2[t] + b2[t]  (X streamed once)
    mma_gemm<false><<<dim3(8, 1024), 256, SMEM_TOTAL>>>(X, nullptr, b1, b2, out,
                                                        nullptr, nullptr);
    // Merged edge sets: out[src] += (E@W5[t] + b5[t]) + w2f[dst]  (softmax singleton = 1)
    mma_gemm<true><<<dim3(4, 1024), 256, SMEM_TOTAL>>>(E0, E1, b5, nullptr, out,
                                                       edges0, edges1);
}

// round 10
// speedup vs baseline: 4.3209x; 1.3479x over previous
#include <cuda_runtime.h>
#include <cuda_fp16.h>
#include <cstdint>

#define NROWS 131072
#define HALFN 65536
#define DDIM  512
#define HDIM  512
#define EPTN  65536

__device__ __half g_w2fh[(size_t)NROWS * HDIM];   // w2f = X@W2+b2, fp16 (128 MB)
__device__ __half g_wh[6u * 512 * 512];           // [z=mat*2+t][n][k] fp16 weights

// SMEM per buffer: A 8K | B 8K = 16K, x2 buffers
#define BUF_STRIDE 16384
#define OFF_A 0
#define OFF_B 8192
#define SMEM_TOTAL (2 * BUF_STRIDE)

#define SWZ64(o) ((o) ^ (((o) >> 3) & 0x30))

__device__ __forceinline__ uint32_t smem_u32(const void* p) {
    uint32_t a;
    asm("{ .reg .u64 t; cvta.to.shared.u64 t, %1; cvt.u32.u64 %0, t; }" : "=r"(a) : "l"(p));
    return a;
}
#define CPASYNC16(dst, src) asm volatile("cp.async.cg.shared.global [%0], [%1], 16;" :: "r"(dst), "l"(src))
#define CPCOMMIT() asm volatile("cp.async.commit_group;" ::: "memory")
#define CPWAIT0()  asm volatile("cp.async.wait_group 0;" ::: "memory")
#define LDSM4(r0, r1, r2, r3, ad) \
    asm volatile("ldmatrix.sync.aligned.m8n8.x4.shared.b16 {%0,%1,%2,%3}, [%4];" \
        : "=r"(r0), "=r"(r1), "=r"(r2), "=r"(r3) : "r"(ad))
#define MMA(d, a, b0, b1) \
    asm volatile("mma.sync.aligned.m16n8k16.row.col.f32.f16.f16.f32 " \
        "{%0,%1,%2,%3}, {%4,%5,%6,%7}, {%8,%9}, {%0,%1,%2,%3};" \
        : "+f"((d)[0]), "+f"((d)[1]), "+f"((d)[2]), "+f"((d)[3]) \
        : "r"((a)[0]), "r"((a)[1]), "r"((a)[2]), "r"((a)[3]), "r"(b0), "r"(b1))
#define REDV2(p, x, y) \
    asm volatile("red.global.add.v2.f32 [%0], {%1, %2};" :: "l"(p), "f"(x), "f"(y) : "memory")

__device__ __forceinline__ uint32_t pack_h2(float a, float b) {
    __half2 h = __floats2half2_rn(a, b);
    return *(uint32_t*)&h;
}

// Transpose W1/W2/W5 into [z][n][k] fp16
__global__ void prep_weights(const float* __restrict__ W1, const float* __restrict__ W2,
                             const float* __restrict__ W5) {
    __shared__ float tile[32][33];
    int z = blockIdx.z, mat = z >> 1, t = z & 1;
    const float* W = (mat == 0 ? W1 : mat == 1 ? W2 : W5) + (size_t)t * 512 * 512;
    int n0 = blockIdx.x * 32, k0 = blockIdx.y * 32;
    int lx = threadIdx.x & 31, ly = threadIdx.x >> 5;
    #pragma unroll
    for (int i = 0; i < 32; i += 8)
        tile[ly + i][lx] = W[(size_t)(k0 + ly + i) * 512 + n0 + lx];
    __syncthreads();
    size_t base = ((size_t)z * 512 + n0) * 512 + k0;
    #pragma unroll
    for (int i = 0; i < 32; i += 8)
        g_wh[base + (size_t)(ly + i) * 512 + lx] = __float2half_rn(tile[lx][ly + i]);
}

// EDGE=false: fused dual-proj. bx in [0,8): mat = bx>>2 (0 -> W1/out(f32), 1 -> W2/w2f(f16)).
// EDGE=true : merged edge sets. by>>9 = set; GEMM(E_set@W5[set]) + gather/scatter epilogue.
template<bool EDGE>
__global__ __launch_bounds__(256, 2)
void mma_gemm(const float* __restrict__ A0, const float* __restrict__ A1,
              const float* __restrict__ bias1, const float* __restrict__ bias2,
              float* __restrict__ out,
              const int* __restrict__ e0, const int* __restrict__ e1)
{
    extern __shared__ char smem[];
    const uint32_t sb = smem_u32(smem);
    const int tid = threadIdx.x, wid = tid >> 5, lane = tid & 31;
    const int bx = blockIdx.x, by = blockIdx.y;
    const int set = EDGE ? (by >> 9) : 0;
    const int ry = (EDGE ? (by & 511) : by) * 128;
    const int cx = (EDGE ? bx : (bx & 3)) * 128;
    const int mat = EDGE ? 2 : (bx >> 2);
    const int t = EDGE ? set : (ry >= HALFN ? 1 : 0);
    const int z = mat * 2 + t;
    const float* A = (EDGE && set) ? A1 : A0;
    const int* edges = EDGE ? (set ? e1 : e0) : nullptr;
    const int wm = wid & 3, wn = wid >> 2;   // warp tile (wm*32, wn*64)

    // ---- fill mappings ----
    const int arow = tid >> 1, ahalf = tid & 1;      // A: 2 thr/row, 16 floats each
    const float4* Ag = (const float4*)(A + (size_t)(ry + arow) * DDIM);
    const int brow = tid >> 1, bhalf = tid & 1;      // B: 2 thr/row, 16 fp16 each
    const __half* BhG = g_wh + ((size_t)z * 512 + cx + brow) * 512 + bhalf * 16;
    const uint32_t a_sts0 = SWZ64(arow * 64 + ahalf * 32);
    const uint32_t a_sts1 = SWZ64(arow * 64 + ahalf * 32 + 16);
    const uint32_t b_dst0 = SWZ64(brow * 64 + bhalf * 32);
    const uint32_t b_dst1 = SWZ64(brow * 64 + bhalf * 32 + 16);

    // ---- ldmatrix per-lane offsets (chunk-independent) ----
    uint32_t a_off[2][2];
    #pragma unroll
    for (int mt = 0; mt < 2; mt++)
        #pragma unroll
        for (int ks = 0; ks < 2; ks++)
            a_off[mt][ks] = SWZ64((wm * 32 + mt * 16 + (lane & 15)) * 64 +
                                  ks * 32 + (lane >> 4) * 16);
    uint32_t b_off[4][2];
    #pragma unroll
    for (int p = 0; p < 4; p++)
        #pragma unroll
        for (int ks = 0; ks < 2; ks++)
            b_off[p][ks] = SWZ64((wn * 64 + p * 16 + (lane & 7) + ((lane & 16) ? 8 : 0)) * 64 +
                                 ks * 32 + ((lane & 8) ? 16 : 0));

    float d[2][8][4];
    #pragma unroll
    for (int i = 0; i < 2; i++)
        #pragma unroll
        for (int j = 0; j < 8; j++)
            #pragma unroll
            for (int q = 0; q < 4; q++) d[i][j][q] = 0.f;

    // ---- prologue: fill buffer 0 (chunk 0) ----
    {
        float4 st[4];
        #pragma unroll
        for (int q = 0; q < 4; q++) st[q] = Ag[ahalf * 4 + q];
        CPASYNC16(sb + OFF_B + b_dst0, BhG);
        CPASYNC16(sb + OFF_B + b_dst1, BhG + 8);
        CPCOMMIT();
        uint4 h0 = {pack_h2(st[0].x, st[0].y), pack_h2(st[0].z, st[0].w),
                    pack_h2(st[1].x, st[1].y), pack_h2(st[1].z, st[1].w)};
        uint4 h1 = {pack_h2(st[2].x, st[2].y), pack_h2(st[2].z, st[2].w),
                    pack_h2(st[3].x, st[3].y), pack_h2(st[3].z, st[3].w)};
        *(uint4*)(smem + OFF_A + a_sts0) = h0;
        *(uint4*)(smem + OFF_A + a_sts1) = h1;
    }

    for (int c = 0; c < 16; c++) {
        const uint32_t buf  = sb + (c & 1) * BUF_STRIDE;
        const uint32_t nbuf = sb + ((c + 1) & 1) * BUF_STRIDE;
        CPWAIT0();
        __syncthreads();

        float4 st[4];
        if (c < 15) {
            #pragma unroll
            for (int q = 0; q < 4; q++) st[q] = Ag[(c + 1) * 8 + ahalf * 4 + q];
            CPASYNC16(nbuf + OFF_B + b_dst0, BhG + (c + 1) * 32);
            CPASYNC16(nbuf + OFF_B + b_dst1, BhG + (c + 1) * 32 + 8);
            CPCOMMIT();
        }

        // ---- compute chunk c: plain fp16 D += A*B ----
        #pragma unroll
        for (int ks = 0; ks < 2; ks++) {
            uint32_t aF[2][4], bh[4][4];
            #pragma unroll
            for (int mt = 0; mt < 2; mt++)
                LDSM4(aF[mt][0], aF[mt][1], aF[mt][2], aF[mt][3], buf + OFF_A + a_off[mt][ks]);
            #pragma unroll
            for (int p = 0; p < 4; p++)
                LDSM4(bh[p][0], bh[p][1], bh[p][2], bh[p][3], buf + OFF_B + b_off[p][ks]);
            #pragma unroll
            for (int p = 0; p < 4; p++)
                #pragma unroll
                for (int mt = 0; mt < 2; mt++) {
                    MMA(d[mt][2 * p],     aF[mt], bh[p][0], bh[p][1]);
                    MMA(d[mt][2 * p + 1], aF[mt], bh[p][2], bh[p][3]);
                }
        }

        if (c < 15) {
            uint4 h0 = {pack_h2(st[0].x, st[0].y), pack_h2(st[0].z, st[0].w),
                        pack_h2(st[1].x, st[1].y), pack_h2(st[1].z, st[1].w)};
            uint4 h1 = {pack_h2(st[2].x, st[2].y), pack_h2(st[2].z, st[2].w),
                        pack_h2(st[3].x, st[3].y), pack_h2(st[3].z, st[3].w)};
            char* nb = smem + ((c + 1) & 1) * BUF_STRIDE;
            *(uint4*)(nb + OFF_A + a_sts0) = h0;
            *(uint4*)(nb + OFF_A + a_sts1) = h1;
        }
    }

    // ---- epilogue ----
    const float* bt = (EDGE ? bias1 : (mat ? bias2 : bias1)) + (size_t)t * HDIM;
    const int c2 = (lane & 3) * 2, gr = lane >> 2;
    const int colw = cx + wn * 64 + c2;
    float2 bv[8];
    #pragma unroll
    for (int n8 = 0; n8 < 8; n8++)
        bv[n8] = *(const float2*)(bt + colw + n8 * 8);

    if (!EDGE) {
        #pragma unroll
        for (int mt = 0; mt < 2; mt++) {
            const int r0 = ry + wm * 32 + mt * 16 + gr;
            if (mat == 0) {
                float* p0 = out + (size_t)r0 * HDIM + colw;
                float* p1 = p0 + (size_t)8 * HDIM;
                #pragma unroll
                for (int n8 = 0; n8 < 8; n8++) {
                    *(float2*)(p0 + n8 * 8) = make_float2(d[mt][n8][0] + bv[n8].x,
                                                          d[mt][n8][1] + bv[n8].y);
                    *(float2*)(p1 + n8 * 8) = make_float2(d[mt][n8][2] + bv[n8].x,
                                                          d[mt][n8][3] + bv[n8].y);
                }
            } else {
                __half* p0 = g_w2fh + (size_t)r0 * HDIM + colw;
                __half* p1 = p0 + (size_t)8 * HDIM;
                #pragma unroll
                for (int n8 = 0; n8 < 8; n8++) {
                    *(__half2*)(p0 + n8 * 8) = __floats2half2_rn(d[mt][n8][0] + bv[n8].x,
                                                                 d[mt][n8][1] + bv[n8].y);
                    *(__half2*)(p1 + n8 * 8) = __floats2half2_rn(d[mt][n8][2] + bv[n8].x,
                                                                 d[mt][n8][3] + bv[n8].y);
                }
            }
        }
    } else {
        #pragma unroll
        for (int mt = 0; mt < 2; mt++) {
            const int e0i = ry + wm * 32 + mt * 16 + gr;
            const int2 ea = ((const int2*)edges)[e0i];
            const int2 eb = ((const int2*)edges)[e0i + 8];
            const __half* wa = g_w2fh + (size_t)ea.y * HDIM + colw;
            const __half* wb = g_w2fh + (size_t)eb.y * HDIM + colw;
            float* oa = out + (size_t)ea.x * HDIM + colw;
            float* ob = out + (size_t)eb.x * HDIM + colw;
            #pragma unroll
            for (int n8 = 0; n8 < 8; n8++) {
                float2 ga = __half22float2(*(const __half2*)(wa + n8 * 8));
                float2 gb = __half22float2(*(const __half2*)(wb + n8 * 8));
                REDV2(oa + n8 * 8, d[mt][n8][0] + bv[n8].x + ga.x,
                                   d[mt][n8][1] + bv[n8].y + ga.y);
                REDV2(ob + n8 * 8, d[mt][n8][2] + bv[n8].x + gb.x,
                                   d[mt][n8][3] + bv[n8].y + gb.y);
            }
        }
    }
}

extern "C" void kernel_launch(void* const* d_in, const int* in_sizes, int n_in,
                              void* d_out, int out_size)
{
    const float* X  = (const float*)d_in[0];
    const float* E0 = (const float*)d_in[1];
    const float* E1 = (const float*)d_in[2];
    const float* W1 = (const float*)d_in[3];
    const float* b1 = (const float*)d_in[4];
    const float* W2 = (const float*)d_in[5];
    const float* b2 = (const float*)d_in[6];
    const float* W5 = (const float*)d_in[11];
    const float* b5 = (const float*)d_in[12];
    const int* edges0 = (const int*)d_in[13];   // JAX x64-disabled: int32 pairs
    const int* edges1 = (const int*)d_in[14];
    float* out = (float*)d_out;

    cudaFuncSetAttribute(mma_gemm<false>, cudaFuncAttributeMaxDynamicSharedMemorySize, SMEM_TOTAL);
    cudaFuncSetAttribute(mma_gemm<true>,  cudaFuncAttributeMaxDynamicSharedMemorySize, SMEM_TOTAL);

    prep_weights<<<dim3(16, 16, 6), 256>>>(W1, W2, W5);
    // Fused: out = X@W1[t] + b1[t]  AND  w2f(fp16) = X@W2[t] + b2[t]  (X streamed once)
    mma_gemm<false><<<dim3(8, 1024), 256, SMEM_TOTAL>>>(X, nullptr, b1, b2, out,
                                                        nullptr, nullptr);
    // Merged edge sets: out[src] += (E@W5[t] + b5[t]) + w2f[dst]  (softmax singleton = 1)
    mma_gemm<true><<<dim3(4, 1024), 256, SMEM_TOTAL>>>(E0, E1, b5, nullptr, out,
                                                       edges0, edges1);
}

// round 12
// speedup vs baseline: 4.7850x; 1.1074x over previous
#include <cuda_runtime.h>
#include <cuda_fp16.h>
#include <cstdint>

#define NROWS 131072
#define HALFN 65536
#define DDIM  512
#define HDIM  512
#define EPTN  65536

__device__ __half g_w2fh[(size_t)NROWS * HDIM];   // w2f = X@W2+b2, fp16 (128 MB)
__device__ __half g_wh[6u * 512 * 512];           // [z=mat*2+t][n][k] fp16 weights
__device__ __half g_xh[(size_t)NROWS * DDIM];     // X in fp16 (128 MB)
__device__ __half g_eh[(size_t)2 * EPTN * DDIM];  // E0|E1 in fp16 (128 MB)

// SMEM per stage: A 8K | B 8K = 16K, x3 stages
#define BUF_STRIDE 16384
#define OFF_A 0
#define OFF_B 8192
#define SMEM_TOTAL (3 * BUF_STRIDE)

#define SWZ64(o) ((o) ^ (((o) >> 3) & 0x30))

__device__ __forceinline__ uint32_t smem_u32(const void* p) {
    uint32_t a;
    asm("{ .reg .u64 t; cvta.to.shared.u64 t, %1; cvt.u32.u64 %0, t; }" : "=r"(a) : "l"(p));
    return a;
}
#define CPASYNC16(dst, src) asm volatile("cp.async.cg.shared.global [%0], [%1], 16;" :: "r"(dst), "l"(src))
#define CPCOMMIT() asm volatile("cp.async.commit_group;" ::: "memory")
#define CPWAIT0()  asm volatile("cp.async.wait_group 0;" ::: "memory")
#define CPWAIT1()  asm volatile("cp.async.wait_group 1;" ::: "memory")
#define LDSM4(r0, r1, r2, r3, ad) \
    asm volatile("ldmatrix.sync.aligned.m8n8.x4.shared.b16 {%0,%1,%2,%3}, [%4];" \
        : "=r"(r0), "=r"(r1), "=r"(r2), "=r"(r3) : "r"(ad))
#define MMA(d, a, b0, b1) \
    asm volatile("mma.sync.aligned.m16n8k16.row.col.f32.f16.f16.f32 " \
        "{%0,%1,%2,%3}, {%4,%5,%6,%7}, {%8,%9}, {%0,%1,%2,%3};" \
        : "+f"((d)[0]), "+f"((d)[1]), "+f"((d)[2]), "+f"((d)[3]) \
        : "r"((a)[0]), "r"((a)[1]), "r"((a)[2]), "r"((a)[3]), "r"(b0), "r"(b1))
#define REDV2(p, x, y) \
    asm volatile("red.global.add.v2.f32 [%0], {%1, %2};" :: "l"(p), "f"(x), "f"(y) : "memory")

__device__ __forceinline__ uint32_t pack_h2(float a, float b) {
    __half2 h = __floats2half2_rn(a, b);
    return *(uint32_t*)&h;
}

// Streaming fp32 -> fp16 convert (same _rn rounding as the old in-loop pack)
__global__ void convert_fp16(const float4* __restrict__ src, __half2* __restrict__ dst,
                             int n4) {
    int i = blockIdx.x * blockDim.x + threadIdx.x;
    if (i < n4) {
        float4 v = src[i];
        uint2 o = {pack_h2(v.x, v.y), pack_h2(v.z, v.w)};
        *(uint2*)(dst + 2 * (size_t)i) = o;
    }
}

// Transpose W1/W2/W5 into [z][n][k] fp16
__global__ void prep_weights(const float* __restrict__ W1, const float* __restrict__ W2,
                             const float* __restrict__ W5) {
    __shared__ float tile[32][33];
    int z = blockIdx.z, mat = z >> 1, t = z & 1;
    const float* W = (mat == 0 ? W1 : mat == 1 ? W2 : W5) + (size_t)t * 512 * 512;
    int n0 = blockIdx.x * 32, k0 = blockIdx.y * 32;
    int lx = threadIdx.x & 31, ly = threadIdx.x >> 5;
    #pragma unroll
    for (int i = 0; i < 32; i += 8)
        tile[ly + i][lx] = W[(size_t)(k0 + ly + i) * 512 + n0 + lx];
    __syncthreads();
    size_t base = ((size_t)z * 512 + n0) * 512 + k0;
    #pragma unroll
    for (int i = 0; i < 32; i += 8)
        g_wh[base + (size_t)(ly + i) * 512 + lx] = __float2half_rn(tile[lx][ly + i]);
}

// EDGE=false: fused dual-proj. bx in [0,8): mat = bx>>2 (0 -> W1/out(f32), 1 -> W2/w2f(f16)).
// EDGE=true : merged edge sets. by>>9 = set; GEMM(E_set@W5[set]) + gather/scatter epilogue.
template<bool EDGE>
__global__ __launch_bounds__(256, 2)
void mma_gemm(const float* __restrict__ bias1, const float* __restrict__ bias2,
              float* __restrict__ out,
              const int* __restrict__ e0, const int* __restrict__ e1)
{
    extern __shared__ char smem[];
    const uint32_t sb = smem_u32(smem);
    const int tid = threadIdx.x, wid = tid >> 5, lane = tid & 31;
    const int bx = blockIdx.x, by = blockIdx.y;
    const int set = EDGE ? (by >> 9) : 0;
    const int ry = (EDGE ? (by & 511) : by) * 128;
    const int cx = (EDGE ? bx : (bx & 3)) * 128;
    const int mat = EDGE ? 2 : (bx >> 2);
    const int t = EDGE ? set : (ry >= HALFN ? 1 : 0);
    const int z = mat * 2 + t;
    const __half* Ah = EDGE ? (g_eh + (size_t)set * EPTN * DDIM) : g_xh;
    const int* edges = EDGE ? (set ? e1 : e0) : nullptr;
    const int wm = wid & 3, wn = wid >> 2;   // warp tile (wm*32, wn*64)

    // ---- cp.async fill mappings (A and B both fp16, 2 thr/row, 32B each) ----
    const int arow = tid >> 1, ahalf = tid & 1;
    const __half* AhG = Ah + (size_t)(ry + arow) * DDIM + ahalf * 16;
    const __half* BhG = g_wh + ((size_t)z * 512 + cx + arow) * 512 + ahalf * 16;
    const uint32_t d0 = SWZ64(arow * 64 + ahalf * 32);
    const uint32_t d1 = SWZ64(arow * 64 + ahalf * 32 + 16);

    // ---- ldmatrix per-lane offsets (chunk-independent) ----
    uint32_t a_off[2][2];
    #pragma unroll
    for (int mt = 0; mt < 2; mt++)
        #pragma unroll
        for (int ks = 0; ks < 2; ks++)
            a_off[mt][ks] = SWZ64((wm * 32 + mt * 16 + (lane & 15)) * 64 +
                                  ks * 32 + (lane >> 4) * 16);
    uint32_t b_off[4][2];
    #pragma unroll
    for (int p = 0; p < 4; p++)
        #pragma unroll
        for (int ks = 0; ks < 2; ks++)
            b_off[p][ks] = SWZ64((wn * 64 + p * 16 + (lane & 7) + ((lane & 16) ? 8 : 0)) * 64 +
                                 ks * 32 + ((lane & 8) ? 16 : 0));

    float d[2][8][4];
    #pragma unroll
    for (int i = 0; i < 2; i++)
        #pragma unroll
        for (int j = 0; j < 8; j++)
            #pragma unroll
            for (int q = 0; q < 4; q++) d[i][j][q] = 0.f;

    // ---- prologue: issue stages for chunks 0 and 1 ----
    // NOTE: second 16-byte copy is +8 halves (= +16 bytes), NOT +16 halves.
    #pragma unroll
    for (int j = 0; j < 2; j++) {
        const uint32_t bb = sb + j * BUF_STRIDE;
        CPASYNC16(bb + OFF_A + d0, AhG + j * 32);
        CPASYNC16(bb + OFF_A + d1, AhG + j * 32 + 8);
        CPASYNC16(bb + OFF_B + d0, BhG + j * 32);
        CPASYNC16(bb + OFF_B + d1, BhG + j * 32 + 8);
        CPCOMMIT();
    }

    int bufi = 0, nbufi = 2;   // buffer index of chunk c; buffer for chunk c+2
    for (int c = 0; c < 16; c++) {
        if (c < 15) CPWAIT1(); else CPWAIT0();
        __syncthreads();

        if (c < 14) {
            const uint32_t bb = sb + nbufi * BUF_STRIDE;
            CPASYNC16(bb + OFF_A + d0, AhG + (c + 2) * 32);
            CPASYNC16(bb + OFF_A + d1, AhG + (c + 2) * 32 + 8);
            CPASYNC16(bb + OFF_B + d0, BhG + (c + 2) * 32);
            CPASYNC16(bb + OFF_B + d1, BhG + (c + 2) * 32 + 8);
            CPCOMMIT();
        }

        // ---- compute chunk c: plain fp16 D += A*B ----
        const uint32_t buf = sb + bufi * BUF_STRIDE;
        #pragma unroll
        for (int ks = 0; ks < 2; ks++) {
            uint32_t aF[2][4], bh[4][4];
            #pragma unroll
            for (int mt = 0; mt < 2; mt++)
                LDSM4(aF[mt][0], aF[mt][1], aF[mt][2], aF[mt][3], buf + OFF_A + a_off[mt][ks]);
            #pragma unroll
            for (int p = 0; p < 4; p++)
                LDSM4(bh[p][0], bh[p][1], bh[p][2], bh[p][3], buf + OFF_B + b_off[p][ks]);
            #pragma unroll
            for (int p = 0; p < 4; p++)
                #pragma unroll
                for (int mt = 0; mt < 2; mt++) {
                    MMA(d[mt][2 * p],     aF[mt], bh[p][0], bh[p][1]);
                    MMA(d[mt][2 * p + 1], aF[mt], bh[p][2], bh[p][3]);
                }
        }

        bufi = (bufi == 2) ? 0 : bufi + 1;
        nbufi = (nbufi == 2) ? 0 : nbufi + 1;
    }

    // ---- epilogue ----
    const float* bt = (EDGE ? bias1 : (mat ? bias2 : bias1)) + (size_t)t * HDIM;
    const int c2 = (lane & 3) * 2, gr = lane >> 2;
    const int colw = cx + wn * 64 + c2;
    float2 bv[8];
    #pragma unroll
    for (int n8 = 0; n8 < 8; n8++)
        bv[n8] = *(const float2*)(bt + colw + n8 * 8);

    if (!EDGE) {
        #pragma unroll
        for (int mt = 0; mt < 2; mt++) {
            const int r0 = ry + wm * 32 + mt * 16 + gr;
            if (mat == 0) {
                float* p0 = out + (size_t)r0 * HDIM + colw;
                float* p1 = p0 + (size_t)8 * HDIM;
                #pragma unroll
                for (int n8 = 0; n8 < 8; n8++) {
                    *(float2*)(p0 + n8 * 8) = make_float2(d[mt][n8][0] + bv[n8].x,
                                                          d[mt][n8][1] + bv[n8].y);
                    *(float2*)(p1 + n8 * 8) = make_float2(d[mt][n8][2] + bv[n8].x,
                                                          d[mt][n8][3] + bv[n8].y);
                }
            } else {
                __half* p0 = g_w2fh + (size_t)r0 * HDIM + colw;
                __half* p1 = p0 + (size_t)8 * HDIM;
                #pragma unroll
                for (int n8 = 0; n8 < 8; n8++) {
                    *(__half2*)(p0 + n8 * 8) = __floats2half2_rn(d[mt][n8][0] + bv[n8].x,
                                                                 d[mt][n8][1] + bv[n8].y);
                    *(__half2*)(p1 + n8 * 8) = __floats2half2_rn(d[mt][n8][2] + bv[n8].x,
                                                                 d[mt][n8][3] + bv[n8].y);
                }
            }
        }
    } else {
        #pragma unroll
        for (int mt = 0; mt < 2; mt++) {
            const int e0i = ry + wm * 32 + mt * 16 + gr;
            const int2 ea = ((const int2*)edges)[e0i];
            const int2 eb = ((const int2*)edges)[e0i + 8];
            const __half* wa = g_w2fh + (size_t)ea.y * HDIM + colw;
            const __half* wb = g_w2fh + (size_t)eb.y * HDIM + colw;
            float* oa = out + (size_t)ea.x * HDIM + colw;
            float* ob = out + (size_t)eb.x * HDIM + colw;
            #pragma unroll
            for (int n8 = 0; n8 < 8; n8++) {
                float2 ga = __half22float2(*(const __half2*)(wa + n8 * 8));
                float2 gb = __half22float2(*(const __half2*)(wb + n8 * 8));
                REDV2(oa + n8 * 8, d[mt][n8][0] + bv[n8].x + ga.x,
                                   d[mt][n8][1] + bv[n8].y + ga.y);
                REDV2(ob + n8 * 8, d[mt][n8][2] + bv[n8].x + gb.x,
                                   d[mt][n8][3] + bv[n8].y + gb.y);
            }
        }
    }
}

extern "C" void kernel_launch(void* const* d_in, const int* in_sizes, int n_in,
                              void* d_out, int out_size)
{
    const float* X  = (const float*)d_in[0];
    const float* E0 = (const float*)d_in[1];
    const float* E1 = (const float*)d_in[2];
    const float* W1 = (const float*)d_in[3];
    const float* b1 = (const float*)d_in[4];
    const float* W2 = (const float*)d_in[5];
    const float* b2 = (const float*)d_in[6];
    const float* W5 = (const float*)d_in[11];
    const float* b5 = (const float*)d_in[12];
    const int* edges0 = (const int*)d_in[13];   // JAX x64-disabled: int32 pairs
    const int* edges1 = (const int*)d_in[14];
    float* out = (float*)d_out;

    __half *xh = nullptr, *eh = nullptr;
    cudaGetSymbolAddress((void**)&xh, g_xh);
    cudaGetSymbolAddress((void**)&eh, g_eh);

    cudaFuncSetAttribute(mma_gemm<false>, cudaFuncAttributeMaxDynamicSharedMemorySize, SMEM_TOTAL);
    cudaFuncSetAttribute(mma_gemm<true>,  cudaFuncAttributeMaxDynamicSharedMemorySize, SMEM_TOTAL);

    // fp32 -> fp16 streaming converts (X, E0, E1)
    const int n4x = NROWS * DDIM / 4;          // 16M float4
    const int n4e = EPTN * DDIM / 4;           // 8M float4
    convert_fp16<<<n4x / 256, 256>>>((const float4*)X, (__half2*)xh, n4x);
    convert_fp16<<<n4e / 256, 256>>>((const float4*)E0, (__half2*)eh, n4e);
    convert_fp16<<<n4e / 256, 256>>>((const float4*)E1,
                                     (__half2*)(eh + (size_t)EPTN * DDIM), n4e);
    prep_weights<<<dim3(16, 16, 6), 256>>>(W1, W2, W5);

    // Fused: out = X@W1[t] + b1[t]  AND  w2f(fp16) = X@W2[t] + b2[t]
    mma_gemm<false><<<dim3(8, 1024), 256, SMEM_TOTAL>>>(b1, b2, out, nullptr, nullptr);
    // Merged edge sets: out[src] += (E@W5[t] + b5[t]) + w2f[dst]  (softmax singleton = 1)
    mma_gemm<true><<<dim3(4, 1024), 256, SMEM_TOTAL>>>(b5, nullptr, out, edges0, edges1);
}